// round 12
// baseline (speedup 1.0000x reference)
#include <cuda_runtime.h>
#include <cuda_fp16.h>
#include <cstdint>

#define S_ 1024
#define B_ 32
#define H_ 512
#define E_ 512
#define A_ 256

// ---------------- device scratch ------------------------------------------------
__device__ __half g_outs_h[(size_t)S_ * B_ * H_];
__device__ __half g_emb_h[(size_t)S_ * B_ * E_];
__device__ __half g_Wenc_h[A_ * E_];
__device__ __half g_Wdec_h[A_ * H_];
__device__ __half g_Wh2h_h[H_ * H_];
__device__ __half g_We2h_h[H_ * E_];
__device__ __half g_emb_att_h[(size_t)S_ * B_ * A_];   // [k*B+b][a]
__device__ __half g_q_att_h[(size_t)S_ * B_ * A_];     // [q*B+b][a]
__device__ __half g_wexp_h[(size_t)B_ * S_ * S_];      // [b][q][k]
__device__ __half g_context_h[(size_t)S_ * B_ * E_];   // [q*B+b][e]
__device__ float  g_rowsum[S_ * B_];                   // [q*B+b]

// ---------------- small helpers -------------------------------------------------
__device__ __forceinline__ __half2 u2h2(uint32_t u) { return *reinterpret_cast<__half2*>(&u); }
__device__ __forceinline__ uint32_t h22u(__half2 h) { return *reinterpret_cast<uint32_t*>(&h); }
__device__ __forceinline__ __half2 tanh2(__half2 x) {
    uint32_t u = h22u(x);
    asm("tanh.approx.f16x2 %0, %0;" : "+r"(u));
    return u2h2(u);
}
__device__ __forceinline__ float tanhf_fast(float x) {
    float y;
    asm("tanh.approx.f32 %0, %1;" : "=f"(y) : "f"(x));
    return y;
}
__device__ __forceinline__ void cpa16(uint32_t s, const void* g) {
    asm volatile("cp.async.cg.shared.global [%0], [%1], 16;" :: "r"(s), "l"(g));
}
#define CP_COMMIT() asm volatile("cp.async.commit_group;" ::: "memory")
#define CP_WAIT1()  asm volatile("cp.async.wait_group 1;" ::: "memory")

__device__ __forceinline__ void ldsm4(uint32_t& r0, uint32_t& r1, uint32_t& r2, uint32_t& r3, uint32_t a) {
    asm volatile("ldmatrix.sync.aligned.m8n8.x4.shared.b16 {%0,%1,%2,%3},[%4];"
                 : "=r"(r0), "=r"(r1), "=r"(r2), "=r"(r3) : "r"(a));
}
__device__ __forceinline__ void ldsm4t(uint32_t& r0, uint32_t& r1, uint32_t& r2, uint32_t& r3, uint32_t a) {
    asm volatile("ldmatrix.sync.aligned.m8n8.x4.trans.shared.b16 {%0,%1,%2,%3},[%4];"
                 : "=r"(r0), "=r"(r1), "=r"(r2), "=r"(r3) : "r"(a));
}
__device__ __forceinline__ void mma16816(float* d, const uint32_t* a, const uint32_t* b) {
    asm volatile("mma.sync.aligned.m16n8k16.row.col.f32.f16.f16.f32 "
                 "{%0,%1,%2,%3},{%4,%5,%6,%7},{%8,%9},{%0,%1,%2,%3};"
                 : "+f"(d[0]), "+f"(d[1]), "+f"(d[2]), "+f"(d[3])
                 : "r"(a[0]), "r"(a[1]), "r"(a[2]), "r"(a[3]), "r"(b[0]), "r"(b[1]));
}

// ---------------- convert fp32 -> fp16 (both big tensors in one launch) ---------
#define BIGN8 ((int)((size_t)S_ * B_ * H_ / 8))
__global__ void __launch_bounds__(256) f2h2_kernel(const float* __restrict__ s0, __half* __restrict__ d0,
                                                   const float* __restrict__ s1, __half* __restrict__ d1) {
    int i = blockIdx.x * blockDim.x + threadIdx.x;
    const float* src; __half* dst; int loc;
    if (i < BIGN8) { src = s0; dst = d0; loc = i; }
    else           { src = s1; dst = d1; loc = i - BIGN8; }
    float4 f0 = reinterpret_cast<const float4*>(src)[loc * 2];
    float4 f1 = reinterpret_cast<const float4*>(src)[loc * 2 + 1];
    __half2 h[4] = { __floats2half2_rn(f0.x, f0.y), __floats2half2_rn(f0.z, f0.w),
                     __floats2half2_rn(f1.x, f1.y), __floats2half2_rn(f1.z, f1.w) };
    reinterpret_cast<uint4*>(dst)[loc] = *reinterpret_cast<uint4*>(h);
}

__global__ void __launch_bounds__(256) f2h_weights_kernel(
    const float* __restrict__ s0, const float* __restrict__ s1,
    const float* __restrict__ s2, const float* __restrict__ s3)
{
    const int N0 = A_ * E_ / 8, N1 = A_ * H_ / 8, N2 = H_ * H_ / 8;
    int i = blockIdx.x * blockDim.x + threadIdx.x;
    const float* src; __half* dst; int loc;
    if (i < N0) { src = s0; dst = g_Wenc_h; loc = i; }
    else if (i < N0 + N1) { src = s1; dst = g_Wdec_h; loc = i - N0; }
    else if (i < N0 + N1 + N2) { src = s2; dst = g_Wh2h_h; loc = i - N0 - N1; }
    else { src = s3; dst = g_We2h_h; loc = i - N0 - N1 - N2; }
    float4 f0 = reinterpret_cast<const float4*>(src)[loc * 2];
    float4 f1 = reinterpret_cast<const float4*>(src)[loc * 2 + 1];
    __half2 h[4] = { __floats2half2_rn(f0.x, f0.y), __floats2half2_rn(f0.z, f0.w),
                     __floats2half2_rn(f1.x, f1.y), __floats2half2_rn(f1.z, f1.w) };
    reinterpret_cast<uint4*>(dst)[loc] = *reinterpret_cast<uint4*>(h);
}

// ---------------- fp16 tensor-core GEMM body (round-8 config, BN=128) -----------
// MODE 0: C(half)[M,N] = A@W^T + bias1 ; optional row remap on A.
// MODE 1: context per b: Chalf[(m*B+b)*E+n] = (1/rowsum)*sum_k wexp_h[b][m][k]*emb_h[(k*B+b)*E+n]
// MODE 2: Cfloat[M,N] = A@W1^T + A2@W2^T + bias1 + bias2 (K=1024 split at 512)
#define BM 128
#define BN 128
#define BK 32
#define STG 3
#define ASTR 40        // halves per A/B0 row (80B)
#define B1STR 136      // halves per B1 row
#define ASZ  (BM * ASTR)     // 5120 halves
#define B0SZ (BN * ASTR)     // 5120
#define B1SZ (BK * B1STR)    // 4352

template<int MODE>
__device__ __forceinline__ void hgemm_body(
    const __half* __restrict__ A, const __half* __restrict__ Bm,
    const __half* __restrict__ A2, const __half* __restrict__ Bm2,
    const float* __restrict__ bias1, const float* __restrict__ bias2,
    void* __restrict__ Cv, int N, int K, int remap,
    int m0, int n0, int b, __half* sh)
{
    const int BSZ = (MODE == 1) ? B1SZ : B0SZ;
    __half* Asm = sh;
    __half* Bsm = sh + STG * ASZ;

    int tid = threadIdx.x;
    const __half* Ap = (MODE == 1) ? (A + (size_t)b * S_ * S_) : A;
    const int KA = (MODE == 1) ? S_ : ((MODE == 2) ? 512 : K);
    const int KB = (MODE == 2) ? 512 : K;

    int wid = tid >> 5, lane = tid & 31;
    int wm = (wid >> 2) * 64, wn = (wid & 3) * 32;

    int Kr = K;
    if (MODE == 1) { int Lmax = max(1, m0 + BM - 2); Kr = min(K, (Lmax + 31) & ~31); }
    int niter = Kr / BK;

    int arow = tid >> 2, ak8 = (tid & 3) * 8;
    int b1row = tid >> 4, b1n8 = (tid & 15) * 8;

    auto copy_stage = [&](int s, int k0) {
        __half* Ad = Asm + s * ASZ;
        __half* Bd = Bsm + s * BSZ;
        const __half* Asrc = Ap; const __half* Bsrc = Bm; int kk = k0;
        if (MODE == 2 && k0 >= 512) { Asrc = A2; Bsrc = Bm2; kk = k0 - 512; }
#pragma unroll
        for (int j = 0; j < 2; j++) {
            int row = arow + j * 64;
            int gr = m0 + row;
            int sr = (MODE == 0 && remap) ? (gr >= B_ ? gr - B_ : gr) : gr;
            cpa16((uint32_t)__cvta_generic_to_shared(Ad + row * ASTR + ak8),
                  Asrc + (size_t)sr * KA + kk + ak8);
        }
        if (MODE == 1) {
#pragma unroll
            for (int j = 0; j < 2; j++) {
                int r = b1row + j * 16;
                cpa16((uint32_t)__cvta_generic_to_shared(Bd + r * B1STR + b1n8),
                      Bm + ((size_t)(k0 + r) * B_ + b) * E_ + n0 + b1n8);
            }
        } else {
#pragma unroll
            for (int j = 0; j < 2; j++) {
                int row = arow + j * 64;
                cpa16((uint32_t)__cvta_generic_to_shared(Bd + row * ASTR + ak8),
                      Bsrc + (size_t)(n0 + row) * KB + kk + ak8);
            }
        }
    };

    uint32_t a_off[4], b_off[2];
    {
        int r = lane & 15, koff = (lane >> 4) * 8;
#pragma unroll
        for (int mt = 0; mt < 4; mt++) {
            int row = wm + mt * 16 + r;
            a_off[mt] = (uint32_t)__cvta_generic_to_shared(Asm + row * ASTR + koff);
        }
        if (MODE == 1) {
            int k = ((lane >> 3) & 1) * 8 + (lane & 7);
#pragma unroll
            for (int p = 0; p < 2; p++) {
                int n = wn + p * 16 + (lane >> 4) * 8;
                b_off[p] = (uint32_t)__cvta_generic_to_shared(Bsm + k * B1STR + n);
            }
        } else {
            int koffb = ((lane >> 3) & 1) * 8;
            int nb = (lane >> 4) * 8 + (lane & 7);
#pragma unroll
            for (int p = 0; p < 2; p++) {
                int n = wn + p * 16 + nb;
                b_off[p] = (uint32_t)__cvta_generic_to_shared(Bsm + n * ASTR + koffb);
            }
        }
    }

    float acc[4][4][4];
#pragma unroll
    for (int i = 0; i < 4; i++)
#pragma unroll
        for (int j = 0; j < 4; j++)
#pragma unroll
            for (int r = 0; r < 4; r++) acc[i][j][r] = 0.f;

#pragma unroll
    for (int s = 0; s < STG - 1; s++) {
        if (s < niter) copy_stage(s, s * BK);
        CP_COMMIT();
    }

    for (int it = 0; it < niter; it++) {
        CP_WAIT1();
        __syncthreads();
        if (it + STG - 1 < niter) copy_stage((it + STG - 1) % STG, (it + STG - 1) * BK);
        CP_COMMIT();

        uint32_t ab = (uint32_t)((it % STG) * ASZ * 2);
        uint32_t bb = (uint32_t)((it % STG) * BSZ * 2);

#pragma unroll
        for (int s = 0; s < 2; s++) {
            uint32_t astep = ab + s * 32;
            uint32_t bstep = (MODE == 1) ? (bb + s * 16 * B1STR * 2) : (bb + s * 32);
            uint32_t af[4][4], bf[2][4];
#pragma unroll
            for (int mt = 0; mt < 4; mt++)
                ldsm4(af[mt][0], af[mt][1], af[mt][2], af[mt][3], a_off[mt] + astep);
#pragma unroll
            for (int p = 0; p < 2; p++) {
                if (MODE == 1) ldsm4t(bf[p][0], bf[p][1], bf[p][2], bf[p][3], b_off[p] + bstep);
                else           ldsm4 (bf[p][0], bf[p][1], bf[p][2], bf[p][3], b_off[p] + bstep);
            }
#pragma unroll
            for (int mt = 0; mt < 4; mt++)
#pragma unroll
                for (int nt = 0; nt < 4; nt++)
                    mma16816(acc[mt][nt], af[mt], &bf[nt >> 1][(nt & 1) * 2]);
        }
        // no trailing sync: next iter's leading barrier protects the stage the
        // next copy overwrites ((it+2)%3 == (it-1)%3, just released above).
    }

    int lr = lane >> 2, lc = lane & 3;
#pragma unroll
    for (int mt = 0; mt < 4; mt++) {
        int mA = m0 + wm + mt * 16 + lr;
        float sc0 = 1.f, sc1 = 1.f;
        if (MODE == 1) {
            sc0 = 1.f / g_rowsum[mA * B_ + b];
            sc1 = 1.f / g_rowsum[(mA + 8) * B_ + b];
        }
#pragma unroll
        for (int nt = 0; nt < 4; nt++) {
            int n = n0 + wn + nt * 8 + lc * 2;
            float* d = acc[mt][nt];
            if (MODE == 0) {
                float a0 = bias1 ? bias1[n] : 0.f, a1 = bias1 ? bias1[n + 1] : 0.f;
                __half* C = (__half*)Cv;
                *reinterpret_cast<__half2*>(&C[(size_t)mA * N + n]) =
                    __floats2half2_rn(d[0] + a0, d[1] + a1);
                *reinterpret_cast<__half2*>(&C[(size_t)(mA + 8) * N + n]) =
                    __floats2half2_rn(d[2] + a0, d[3] + a1);
            } else if (MODE == 1) {
                __half* C = (__half*)Cv;
                *reinterpret_cast<__half2*>(&C[((size_t)mA * B_ + b) * E_ + n]) =
                    __floats2half2_rn(d[0] * sc0, d[1] * sc0);
                *reinterpret_cast<__half2*>(&C[((size_t)(mA + 8) * B_ + b) * E_ + n]) =
                    __floats2half2_rn(d[2] * sc1, d[3] * sc1);
            } else {
                float a0 = bias1[n] + bias2[n], a1 = bias1[n + 1] + bias2[n + 1];
                float* C = (float*)Cv;
                float2 v0 = {d[0] + a0, d[1] + a1};
                float2 v1 = {d[2] + a0, d[3] + a1};
                *reinterpret_cast<float2*>(&C[(size_t)mA * N + n]) = v0;
                *reinterpret_cast<float2*>(&C[(size_t)(mA + 8) * N + n]) = v1;
            }
        }
    }
}

template<int MODE>
__global__ void __launch_bounds__(256, 2) hgemm(
    const __half* __restrict__ A, const __half* __restrict__ Bm,
    const __half* __restrict__ A2, const __half* __restrict__ Bm2,
    const float* __restrict__ bias1, const float* __restrict__ bias2,
    void* __restrict__ Cv, int N, int K, int remap)
{
    extern __shared__ __half sh[];
    hgemm_body<MODE>(A, Bm, A2, Bm2, bias1, bias2, Cv, N, K, remap,
                     blockIdx.x * BM, blockIdx.y * BN, blockIdx.z, sh);
}

// both projections in one launch: z=0 -> emb_att, z=1 -> q_att (remapped rows)
__global__ void __launch_bounds__(256, 2) hgemm_proj2(
    const float* __restrict__ b_enc, const float* __restrict__ b_dec)
{
    extern __shared__ __half sh[];
    if (blockIdx.z == 0)
        hgemm_body<0>(g_emb_h, g_Wenc_h, nullptr, nullptr, b_enc, nullptr,
                      g_emb_att_h, A_, E_, 0, blockIdx.x * BM, blockIdx.y * BN, 0, sh);
    else
        hgemm_body<0>(g_outs_h, g_Wdec_h, nullptr, nullptr, b_dec, nullptr,
                      g_q_att_h, A_, H_, 1, blockIdx.x * BM, blockIdx.y * BN, 0, sh);
}

// ---------------- scores: MUFU(6 keys) + LUT(2 keys) hybrid tanh ----------------
#define SQ 16
#define QA2STR 257
// smem words: ea2 16384 | qa2 4112 | vs2 256 | vs_f 256 | qb_f 4112 | lut 512 | sums 16
#define SCORE_W (16384 + 4112 + 256 + 256 + 4112 + 512 + 16)
#define SCORE_SMEM (SCORE_W * 4)

__global__ void __launch_bounds__(256) score_kernel(const float* __restrict__ v)
{
    extern __shared__ uint32_t sw[];
    uint32_t* ea2 = sw;                         // [256 a][64 k2] half2
    uint32_t* qa2 = sw + 16384;                 // [16 q][257] dup-half2
    uint32_t* vs2 = qa2 + SQ * QA2STR;          // [256] dup-half2
    float*   vs_f = (float*)(vs2 + 256);        // [256] fp32 v
    float*   qb_f = vs_f + 256;                 // [16 q][257] qa*32+128
    float2*  lut  = (float2*)(qb_f + SQ * QA2STR); // [256] (tanh, dtanh)
    float*   sums = (float*)(lut + 256);        // [16]

    int tid = threadIdx.x;
    int q0 = blockIdx.x * SQ, b = blockIdx.y;
    int q = tid & 15, kq = tid >> 4, w = tid >> 5;
    int qg = q0 + q;
    int Lq = max(1, qg - 1);

    {
        float vv = v[tid];
        vs2[tid] = h22u(__floats2half2_rn(vv, vv));
        vs_f[tid] = vv;
        float xt = (float)(tid - 128) * 0.03125f;
        float t0 = tanhf_fast(xt);
        float t1 = tanhf_fast(xt + 0.03125f);
        lut[tid] = make_float2(t0, t1 - t0);
    }
    if (tid < SQ) sums[tid] = 0.f;
#pragma unroll
    for (int it = 0; it < 2; it++) {
        int lin = tid + it * 256;
        int qq = lin >> 5, a8 = lin & 31;
        uint4 u = *reinterpret_cast<const uint4*>(
            g_q_att_h + ((size_t)(q0 + qq) * B_ + b) * A_ + a8 * 8);
        __half h[8]; *reinterpret_cast<uint4*>(h) = u;
#pragma unroll
        for (int i = 0; i < 8; i++) {
            qa2[qq * QA2STR + a8 * 8 + i] = h22u(__half2half2(h[i]));
            qb_f[qq * QA2STR + a8 * 8 + i] = fmaf(__half2float(h[i]), 32.f, 128.f);
        }
    }

    int Lmax = max(1, q0 + SQ - 2);
    size_t wrow = ((size_t)b * S_ + qg) * S_;
    const __half2 hz = __floats2half2_rn(0.f, 0.f);

    for (int k0 = 0; k0 < Lmax; k0 += 128) {
        __syncthreads();
#pragma unroll
        for (int it = 0; it < 8; it++) {
            int lin = tid + it * 256;
            int k2 = lin & 63, a8 = lin >> 6;
            const __half* p = g_emb_att_h + ((size_t)(k0 + 2 * k2) * B_ + b) * A_ + a8 * 8;
            uint4 u0 = *reinterpret_cast<const uint4*>(p);
            uint4 u1 = *reinterpret_cast<const uint4*>(p + (size_t)B_ * A_);
            __half h0[8], h1[8];
            *reinterpret_cast<uint4*>(h0) = u0;
            *reinterpret_cast<uint4*>(h1) = u1;
#pragma unroll
            for (int i = 0; i < 8; i++)
                ea2[(a8 * 8 + i) * 64 + k2] = h22u(__halves2half2(h0[i], h1[i]));
        }
        __syncthreads();

        int kb = k0 + kq * 8;
        if (k0 + 16 * w < Lmax) {
            float facc[8] = {0.f, 0.f, 0.f, 0.f, 0.f, 0.f, 0.f, 0.f};
            for (int a0 = 0; a0 < A_; a0 += 8) {
                __half2 h0 = hz, h1 = hz, h2 = hz;
#pragma unroll
                for (int aa = 0; aa < 8; aa++) {
                    int a = a0 + aa;
                    uint4 e = *reinterpret_cast<uint4*>(&ea2[a * 64 + kq * 4]);
                    __half2 qh = u2h2(qa2[q * QA2STR + a]);
                    __half2 v2 = u2h2(vs2[a]);
                    // keys 0-5: MUFU tanh2
                    h0 = __hfma2(v2, tanh2(__hadd2(qh, u2h2(e.x))), h0);
                    h1 = __hfma2(v2, tanh2(__hadd2(qh, u2h2(e.y))), h1);
                    h2 = __hfma2(v2, tanh2(__hadd2(qh, u2h2(e.z))), h2);
                    // keys 6-7: shared-memory LUT (linear interp, FMA pipe)
                    float2 ef = __half22float2(u2h2(e.w));
                    float qb = qb_f[q * QA2STR + a];
                    float vf = vs_f[a];
                    float i0 = fmaf(ef.x, 32.f, qb);
                    float i1 = fmaf(ef.y, 32.f, qb);
                    i0 = fminf(fmaxf(i0, 0.f), 255.5f);
                    i1 = fminf(fmaxf(i1, 0.f), 255.5f);
                    int n0i = (int)i0;
                    int n1i = (int)i1;
                    float fr0 = i0 - (float)n0i;
                    float fr1 = i1 - (float)n1i;
                    float2 l0 = lut[n0i];
                    float2 l1 = lut[n1i];
                    facc[6] = fmaf(vf, fmaf(l0.y, fr0, l0.x), facc[6]);
                    facc[7] = fmaf(vf, fmaf(l1.y, fr1, l1.x), facc[7]);
                }
                float2 t0 = __half22float2(h0), t1 = __half22float2(h1);
                float2 t2 = __half22float2(h2);
                facc[0] += t0.x; facc[1] += t0.y; facc[2] += t1.x; facc[3] += t1.y;
                facc[4] += t2.x; facc[5] += t2.y;
            }

            float sl = 0.f;
            __half2 o[4];
#pragma unroll
            for (int j = 0; j < 4; j++) {
                float w0 = (kb + 2 * j     < Lq) ? __expf(facc[2 * j])     : 0.f;
                float w1 = (kb + 2 * j + 1 < Lq) ? __expf(facc[2 * j + 1]) : 0.f;
                sl += w0 + w1;
                o[j] = __floats2half2_rn(w0, w1);
            }
            *reinterpret_cast<uint4*>(&g_wexp_h[wrow + kb]) = *reinterpret_cast<uint4*>(o);
            atomicAdd(&sums[q], sl);
        } else {
            uint4 z = {0u, 0u, 0u, 0u};
            *reinterpret_cast<uint4*>(&g_wexp_h[wrow + kb]) = z;
        }
    }
    __syncthreads();
    if (tid < SQ) g_rowsum[(q0 + tid) * B_ + b] = sums[tid];
}

// ---------------- normalize + transpose (b,q,k) -> weights (q,k,b) -------------
__global__ void __launch_bounds__(256) norm_transpose_kernel(float* __restrict__ wout)
{
    __shared__ float tile[32][33];
    __shared__ float inv_s[32];
    int tid = threadIdx.x;
    int q = blockIdx.y;
    int k0 = blockIdx.x * 32;
    int tx = tid & 31;
    int ty = tid >> 5;
    int Lq = max(1, q - 1);
    if (tid < 32) inv_s[tid] = 1.f / g_rowsum[q * B_ + tid];
#pragma unroll
    for (int i = 0; i < 4; i++) {
        int bb = ty + i * 8;
        tile[bb][tx] = __half2float(g_wexp_h[((size_t)bb * S_ + q) * S_ + k0 + tx]);
    }
    __syncthreads();
#pragma unroll
    for (int i = 0; i < 4; i++) {
        int kk = ty + i * 8;
        float val = (k0 + kk < Lq) ? tile[tx][kk] * inv_s[tx] : 0.f;
        wout[((size_t)q * S_ + k0 + kk) * B_ + tx] = val;
    }
}

// ---------------- launch --------------------------------------------------------
extern "C" void kernel_launch(void* const* d_in, const int* in_sizes, int n_in,
                              void* d_out, int out_size)
{
    const float* outs  = (const float*)d_in[0];
    const float* emb   = (const float*)d_in[1];
    const float* W_enc = (const float*)d_in[2];
    const float* b_enc = (const float*)d_in[3];
    const float* W_dec = (const float*)d_in[4];
    const float* b_dec = (const float*)d_in[5];
    const float* v     = (const float*)d_in[6];
    const float* W_h2h = (const float*)d_in[7];
    const float* b_h2h = (const float*)d_in[8];
    const float* W_e2h = (const float*)d_in[9];
    const float* b_e2h = (const float*)d_in[10];
    float* out = (float*)d_out;

    __half *p_outs_h, *p_emb_h, *p_wexp, *p_ctx, *p_Wh2h, *p_We2h;
    cudaGetSymbolAddress((void**)&p_outs_h, g_outs_h);
    cudaGetSymbolAddress((void**)&p_emb_h, g_emb_h);
    cudaGetSymbolAddress((void**)&p_Wh2h, g_Wh2h_h);
    cudaGetSymbolAddress((void**)&p_We2h, g_We2h_h);
    cudaGetSymbolAddress((void**)&p_wexp, g_wexp_h);
    cudaGetSymbolAddress((void**)&p_ctx, g_context_h);

    const int SMEM0 = STG * (ASZ + B0SZ) * 2;   // 61440 B
    const int SMEM1 = STG * (ASZ + B1SZ) * 2;   // 56832 B
    cudaFuncSetAttribute(hgemm_proj2, cudaFuncAttributeMaxDynamicSharedMemorySize, SMEM0);
    cudaFuncSetAttribute(hgemm<1>, cudaFuncAttributeMaxDynamicSharedMemorySize, SMEM1);
    cudaFuncSetAttribute(hgemm<2>, cudaFuncAttributeMaxDynamicSharedMemorySize, SMEM0);
    cudaFuncSetAttribute(score_kernel, cudaFuncAttributeMaxDynamicSharedMemorySize, SCORE_SMEM);

    const size_t OUT1 = (size_t)S_ * B_ * H_;
    const size_t WSZ  = (size_t)S_ * S_ * B_;
    bool hasW = ((size_t)out_size >= OUT1 + WSZ);

    // 0-1. convert inputs to fp16
    f2h2_kernel<<<16384, 256>>>(outs, p_outs_h, emb, p_emb_h);
    f2h_weights_kernel<<<384, 256>>>(W_enc, W_dec, W_h2h, W_e2h);

    // 2. both projections in one launch
    hgemm_proj2<<<dim3((S_ * B_) / BM, A_ / BN, 2), 256, SMEM0>>>(b_enc, b_dec);

    // 3. scores + exp + rowsums (hybrid MUFU/LUT tanh)
    score_kernel<<<dim3(S_ / SQ, B_), 256, SCORE_SMEM>>>(v);

    // 4. normalized weights output (q,k,b)
    if (hasW)
        norm_transpose_kernel<<<dim3(S_ / 32, S_), 256>>>(out + OUT1);

    // 5. context (triangular K, fused 1/rowsum, half out) — ncu capture target
    hgemm<1><<<dim3(S_ / BM, E_ / BN, B_), 256, SMEM1>>>(
        p_wexp, p_emb_h, nullptr, nullptr, nullptr, nullptr, p_ctx, E_, S_, 0);

    // 6. output = outs@W_h2h^T + ctx@W_e2h^T + biases (fused dual-K)
    hgemm<2><<<dim3((S_ * B_) / BM, H_ / BN), 256, SMEM0>>>(
        p_outs_h, p_Wh2h, p_ctx, p_We2h, b_h2h, b_e2h, out, H_, 1024, 0);
}

// round 13
// speedup vs baseline: 1.1760x; 1.1760x over previous
#include <cuda_runtime.h>
#include <cuda_fp16.h>
#include <cstdint>

#define S_ 1024
#define B_ 32
#define H_ 512
#define E_ 512
#define A_ 256

// ---------------- device scratch ------------------------------------------------
__device__ __half g_outs_h[(size_t)S_ * B_ * H_];
__device__ __half g_emb_h[(size_t)S_ * B_ * E_];
__device__ __half g_Wenc_h[A_ * E_];
__device__ __half g_Wdec_h[A_ * H_];
__device__ __half g_Wh2h_h[H_ * H_];
__device__ __half g_We2h_h[H_ * E_];
__device__ __half g_emb_att_h[(size_t)S_ * B_ * A_];   // [k*B+b][a]
__device__ __half g_q_att_h[(size_t)S_ * B_ * A_];     // [q*B+b][a]
__device__ __half g_wexp_h[(size_t)B_ * S_ * S_];      // [b][q][k]
__device__ __half g_context_h[(size_t)S_ * B_ * E_];   // [q*B+b][e]
__device__ float  g_rowsum[S_ * B_];                   // [q*B+b]

// ---------------- small helpers -------------------------------------------------
__device__ __forceinline__ __half2 u2h2(uint32_t u) { return *reinterpret_cast<__half2*>(&u); }
__device__ __forceinline__ uint32_t h22u(__half2 h) { return *reinterpret_cast<uint32_t*>(&h); }
__device__ __forceinline__ __half2 tanh2(__half2 x) {
    uint32_t u = h22u(x);
    asm("tanh.approx.f16x2 %0, %0;" : "+r"(u));
    return u2h2(u);
}
__device__ __forceinline__ void cpa16(uint32_t s, const void* g) {
    asm volatile("cp.async.cg.shared.global [%0], [%1], 16;" :: "r"(s), "l"(g));
}
#define CP_COMMIT() asm volatile("cp.async.commit_group;" ::: "memory")
#define CP_WAIT1()  asm volatile("cp.async.wait_group 1;" ::: "memory")

__device__ __forceinline__ void ldsm4(uint32_t& r0, uint32_t& r1, uint32_t& r2, uint32_t& r3, uint32_t a) {
    asm volatile("ldmatrix.sync.aligned.m8n8.x4.shared.b16 {%0,%1,%2,%3},[%4];"
                 : "=r"(r0), "=r"(r1), "=r"(r2), "=r"(r3) : "r"(a));
}
__device__ __forceinline__ void ldsm4t(uint32_t& r0, uint32_t& r1, uint32_t& r2, uint32_t& r3, uint32_t a) {
    asm volatile("ldmatrix.sync.aligned.m8n8.x4.trans.shared.b16 {%0,%1,%2,%3},[%4];"
                 : "=r"(r0), "=r"(r1), "=r"(r2), "=r"(r3) : "r"(a));
}
__device__ __forceinline__ void mma16816(float* d, const uint32_t* a, const uint32_t* b) {
    asm volatile("mma.sync.aligned.m16n8k16.row.col.f32.f16.f16.f32 "
                 "{%0,%1,%2,%3},{%4,%5,%6,%7},{%8,%9},{%0,%1,%2,%3};"
                 : "+f"(d[0]), "+f"(d[1]), "+f"(d[2]), "+f"(d[3])
                 : "r"(a[0]), "r"(a[1]), "r"(a[2]), "r"(a[3]), "r"(b[0]), "r"(b[1]));
}

// ---------------- convert ALL fp32 inputs -> fp16 in ONE launch ------------------
#define BIGN8 ((int)((size_t)S_ * B_ * H_ / 8))
#define WN0 (A_ * E_ / 8)
#define WN1 (A_ * H_ / 8)
#define WN2 (H_ * H_ / 8)
#define WN3 (H_ * E_ / 8)
// total float8 groups: 2*BIGN8 + WN0+WN1+WN2+WN3 = 4,292,608 -> grid 16768 x 256
__global__ void __launch_bounds__(256) f2h_all_kernel(
    const float* __restrict__ outs, const float* __restrict__ emb,
    const float* __restrict__ w0, const float* __restrict__ w1,
    const float* __restrict__ w2, const float* __restrict__ w3)
{
    int i = blockIdx.x * blockDim.x + threadIdx.x;
    const float* src; __half* dst; int loc;
    if (i < BIGN8)            { src = outs; dst = g_outs_h; loc = i; }
    else if (i < 2 * BIGN8)   { src = emb;  dst = g_emb_h;  loc = i - BIGN8; }
    else {
        int j = i - 2 * BIGN8;
        if (j < WN0)                    { src = w0; dst = g_Wenc_h; loc = j; }
        else if (j < WN0 + WN1)         { src = w1; dst = g_Wdec_h; loc = j - WN0; }
        else if (j < WN0 + WN1 + WN2)   { src = w2; dst = g_Wh2h_h; loc = j - WN0 - WN1; }
        else                            { src = w3; dst = g_We2h_h; loc = j - WN0 - WN1 - WN2; }
    }
    float4 f0 = reinterpret_cast<const float4*>(src)[loc * 2];
    float4 f1 = reinterpret_cast<const float4*>(src)[loc * 2 + 1];
    __half2 h[4] = { __floats2half2_rn(f0.x, f0.y), __floats2half2_rn(f0.z, f0.w),
                     __floats2half2_rn(f1.x, f1.y), __floats2half2_rn(f1.z, f1.w) };
    reinterpret_cast<uint4*>(dst)[loc] = *reinterpret_cast<uint4*>(h);
}

// ---------------- fp16 tensor-core GEMM body (BN=128, BK=32, STG=3) -------------
// MODE 0: C(half)[M,N] = A@W^T + bias1 ; optional row remap on A.
// MODE 1: context per b: Chalf[(m*B+b)*E+n] = (1/rowsum)*sum_k wexp_h[b][m][k]*emb_h[(k*B+b)*E+n]
// MODE 2: Cfloat[M,N] = A@W1^T + A2@W2^T + bias1 + bias2 (K=1024 split at 512)
#define BM 128
#define BN 128
#define BK 32
#define STG 3
#define ASTR 40        // halves per A/B0 row (80B)
#define B1STR 136      // halves per B1 row
#define ASZ  (BM * ASTR)     // 5120 halves
#define B0SZ (BN * ASTR)     // 5120
#define B1SZ (BK * B1STR)    // 4352

template<int MODE>
__device__ __forceinline__ void hgemm_body(
    const __half* __restrict__ A, const __half* __restrict__ Bm,
    const __half* __restrict__ A2, const __half* __restrict__ Bm2,
    const float* __restrict__ bias1, const float* __restrict__ bias2,
    void* __restrict__ Cv, int N, int K, int remap,
    int m0, int n0, int b, __half* sh)
{
    const int BSZ = (MODE == 1) ? B1SZ : B0SZ;
    __half* Asm = sh;
    __half* Bsm = sh + STG * ASZ;

    int tid = threadIdx.x;
    const __half* Ap = (MODE == 1) ? (A + (size_t)b * S_ * S_) : A;
    const int KA = (MODE == 1) ? S_ : ((MODE == 2) ? 512 : K);
    const int KB = (MODE == 2) ? 512 : K;

    int wid = tid >> 5, lane = tid & 31;
    int wm = (wid >> 2) * 64, wn = (wid & 3) * 32;

    int Kr = K;
    if (MODE == 1) { int Lmax = max(1, m0 + BM - 2); Kr = min(K, (Lmax + 31) & ~31); }
    int niter = Kr / BK;

    int arow = tid >> 2, ak8 = (tid & 3) * 8;
    int b1row = tid >> 4, b1n8 = (tid & 15) * 8;

    auto copy_stage = [&](int s, int k0) {
        __half* Ad = Asm + s * ASZ;
        __half* Bd = Bsm + s * BSZ;
        const __half* Asrc = Ap; const __half* Bsrc = Bm; int kk = k0;
        if (MODE == 2 && k0 >= 512) { Asrc = A2; Bsrc = Bm2; kk = k0 - 512; }
#pragma unroll
        for (int j = 0; j < 2; j++) {
            int row = arow + j * 64;
            int gr = m0 + row;
            int sr = (MODE == 0 && remap) ? (gr >= B_ ? gr - B_ : gr) : gr;
            cpa16((uint32_t)__cvta_generic_to_shared(Ad + row * ASTR + ak8),
                  Asrc + (size_t)sr * KA + kk + ak8);
        }
        if (MODE == 1) {
#pragma unroll
            for (int j = 0; j < 2; j++) {
                int r = b1row + j * 16;
                cpa16((uint32_t)__cvta_generic_to_shared(Bd + r * B1STR + b1n8),
                      Bm + ((size_t)(k0 + r) * B_ + b) * E_ + n0 + b1n8);
            }
        } else {
#pragma unroll
            for (int j = 0; j < 2; j++) {
                int row = arow + j * 64;
                cpa16((uint32_t)__cvta_generic_to_shared(Bd + row * ASTR + ak8),
                      Bsrc + (size_t)(n0 + row) * KB + kk + ak8);
            }
        }
    };

    uint32_t a_off[4], b_off[2];
    {
        int r = lane & 15, koff = (lane >> 4) * 8;
#pragma unroll
        for (int mt = 0; mt < 4; mt++) {
            int row = wm + mt * 16 + r;
            a_off[mt] = (uint32_t)__cvta_generic_to_shared(Asm + row * ASTR + koff);
        }
        if (MODE == 1) {
            int k = ((lane >> 3) & 1) * 8 + (lane & 7);
#pragma unroll
            for (int p = 0; p < 2; p++) {
                int n = wn + p * 16 + (lane >> 4) * 8;
                b_off[p] = (uint32_t)__cvta_generic_to_shared(Bsm + k * B1STR + n);
            }
        } else {
            int koffb = ((lane >> 3) & 1) * 8;
            int nb = (lane >> 4) * 8 + (lane & 7);
#pragma unroll
            for (int p = 0; p < 2; p++) {
                int n = wn + p * 16 + nb;
                b_off[p] = (uint32_t)__cvta_generic_to_shared(Bsm + n * ASTR + koffb);
            }
        }
    }

    float acc[4][4][4];
#pragma unroll
    for (int i = 0; i < 4; i++)
#pragma unroll
        for (int j = 0; j < 4; j++)
#pragma unroll
            for (int r = 0; r < 4; r++) acc[i][j][r] = 0.f;

#pragma unroll
    for (int s = 0; s < STG - 1; s++) {
        if (s < niter) copy_stage(s, s * BK);
        CP_COMMIT();
    }

    for (int it = 0; it < niter; it++) {
        CP_WAIT1();
        __syncthreads();
        if (it + STG - 1 < niter) copy_stage((it + STG - 1) % STG, (it + STG - 1) * BK);
        CP_COMMIT();

        uint32_t ab = (uint32_t)((it % STG) * ASZ * 2);
        uint32_t bb = (uint32_t)((it % STG) * BSZ * 2);

#pragma unroll
        for (int s = 0; s < 2; s++) {
            uint32_t astep = ab + s * 32;
            uint32_t bstep = (MODE == 1) ? (bb + s * 16 * B1STR * 2) : (bb + s * 32);
            uint32_t af[4][4], bf[2][4];
#pragma unroll
            for (int mt = 0; mt < 4; mt++)
                ldsm4(af[mt][0], af[mt][1], af[mt][2], af[mt][3], a_off[mt] + astep);
#pragma unroll
            for (int p = 0; p < 2; p++) {
                if (MODE == 1) ldsm4t(bf[p][0], bf[p][1], bf[p][2], bf[p][3], b_off[p] + bstep);
                else           ldsm4 (bf[p][0], bf[p][1], bf[p][2], bf[p][3], b_off[p] + bstep);
            }
#pragma unroll
            for (int mt = 0; mt < 4; mt++)
#pragma unroll
                for (int nt = 0; nt < 4; nt++)
                    mma16816(acc[mt][nt], af[mt], &bf[nt >> 1][(nt & 1) * 2]);
        }
        // no trailing sync: next iter's leading barrier protects the stage the
        // next copy overwrites ((it+2)%3 == (it-1)%3, released by that barrier).
    }

    int lr = lane >> 2, lc = lane & 3;
#pragma unroll
    for (int mt = 0; mt < 4; mt++) {
        int mA = m0 + wm + mt * 16 + lr;
        float sc0 = 1.f, sc1 = 1.f;
        if (MODE == 1) {
            sc0 = 1.f / g_rowsum[mA * B_ + b];
            sc1 = 1.f / g_rowsum[(mA + 8) * B_ + b];
        }
#pragma unroll
        for (int nt = 0; nt < 4; nt++) {
            int n = n0 + wn + nt * 8 + lc * 2;
            float* d = acc[mt][nt];
            if (MODE == 0) {
                float a0 = bias1 ? bias1[n] : 0.f, a1 = bias1 ? bias1[n + 1] : 0.f;
                __half* C = (__half*)Cv;
                *reinterpret_cast<__half2*>(&C[(size_t)mA * N + n]) =
                    __floats2half2_rn(d[0] + a0, d[1] + a1);
                *reinterpret_cast<__half2*>(&C[(size_t)(mA + 8) * N + n]) =
                    __floats2half2_rn(d[2] + a0, d[3] + a1);
            } else if (MODE == 1) {
                __half* C = (__half*)Cv;
                *reinterpret_cast<__half2*>(&C[((size_t)mA * B_ + b) * E_ + n]) =
                    __floats2half2_rn(d[0] * sc0, d[1] * sc0);
                *reinterpret_cast<__half2*>(&C[((size_t)(mA + 8) * B_ + b) * E_ + n]) =
                    __floats2half2_rn(d[2] * sc1, d[3] * sc1);
            } else {
                float a0 = bias1[n] + bias2[n], a1 = bias1[n + 1] + bias2[n + 1];
                float* C = (float*)Cv;
                float2 v0 = {d[0] + a0, d[1] + a1};
                float2 v1 = {d[2] + a0, d[3] + a1};
                *reinterpret_cast<float2*>(&C[(size_t)mA * N + n]) = v0;
                *reinterpret_cast<float2*>(&C[(size_t)(mA + 8) * N + n]) = v1;
            }
        }
    }
}

template<int MODE>
__global__ void __launch_bounds__(256, 2) hgemm(
    const __half* __restrict__ A, const __half* __restrict__ Bm,
    const __half* __restrict__ A2, const __half* __restrict__ Bm2,
    const float* __restrict__ bias1, const float* __restrict__ bias2,
    void* __restrict__ Cv, int N, int K, int remap)
{
    extern __shared__ __half sh[];
    hgemm_body<MODE>(A, Bm, A2, Bm2, bias1, bias2, Cv, N, K, remap,
                     blockIdx.x * BM, blockIdx.y * BN, blockIdx.z, sh);
}

// both projections in one launch: z=0 -> emb_att, z=1 -> q_att (remapped rows)
__global__ void __launch_bounds__(256, 2) hgemm_proj2(
    const float* __restrict__ b_enc, const float* __restrict__ b_dec)
{
    extern __shared__ __half sh[];
    if (blockIdx.z == 0)
        hgemm_body<0>(g_emb_h, g_Wenc_h, nullptr, nullptr, b_enc, nullptr,
                      g_emb_att_h, A_, E_, 0, blockIdx.x * BM, blockIdx.y * BN, 0, sh);
    else
        hgemm_body<0>(g_outs_h, g_Wdec_h, nullptr, nullptr, b_dec, nullptr,
                      g_q_att_h, A_, H_, 1, blockIdx.x * BM, blockIdx.y * BN, 0, sh);
}

// ---------------- scores: pure-MUFU tanh2, warp-contiguous-k + triangular skip --
#define SQ 16
#define QA2STR 257
#define SCORE_W (16384 + SQ * QA2STR + 256 + 16)
#define SCORE_SMEM (SCORE_W * 4)

__global__ void __launch_bounds__(256) score_kernel(const float* __restrict__ v)
{
    extern __shared__ uint32_t sw[];
    uint32_t* ea2 = sw;                        // [256 a][64 k2] half2
    uint32_t* qa2 = sw + 16384;                // [16 q][257] dup-half2
    uint32_t* vs2 = sw + 16384 + SQ * QA2STR;  // [256] dup-half2
    float* sums = (float*)(vs2 + 256);         // [16]

    int tid = threadIdx.x;
    int q0 = blockIdx.x * SQ, b = blockIdx.y;
    int q = tid & 15, kq = tid >> 4, w = tid >> 5;
    int qg = q0 + q;
    int Lq = max(1, qg - 1);

    vs2[tid] = h22u(__floats2half2_rn(v[tid], v[tid]));
    if (tid < SQ) sums[tid] = 0.f;
#pragma unroll
    for (int it = 0; it < 2; it++) {
        int lin = tid + it * 256;
        int qq = lin >> 5, a8 = lin & 31;
        uint4 u = *reinterpret_cast<const uint4*>(
            g_q_att_h + ((size_t)(q0 + qq) * B_ + b) * A_ + a8 * 8);
        __half h[8]; *reinterpret_cast<uint4*>(h) = u;
#pragma unroll
        for (int i = 0; i < 8; i++)
            qa2[qq * QA2STR + a8 * 8 + i] = h22u(__half2half2(h[i]));
    }

    int Lmax = max(1, q0 + SQ - 2);
    size_t wrow = ((size_t)b * S_ + qg) * S_;
    const __half2 hz = __floats2half2_rn(0.f, 0.f);

    for (int k0 = 0; k0 < Lmax; k0 += 128) {
        __syncthreads();
#pragma unroll
        for (int it = 0; it < 8; it++) {
            int lin = tid + it * 256;
            int k2 = lin & 63, a8 = lin >> 6;
            const __half* p = g_emb_att_h + ((size_t)(k0 + 2 * k2) * B_ + b) * A_ + a8 * 8;
            uint4 u0 = *reinterpret_cast<const uint4*>(p);
            uint4 u1 = *reinterpret_cast<const uint4*>(p + (size_t)B_ * A_);
            __half h0[8], h1[8];
            *reinterpret_cast<uint4*>(h0) = u0;
            *reinterpret_cast<uint4*>(h1) = u1;
#pragma unroll
            for (int i = 0; i < 8; i++)
                ea2[(a8 * 8 + i) * 64 + k2] = h22u(__halves2half2(h0[i], h1[i]));
        }
        __syncthreads();

        int kb = k0 + kq * 8;
        if (k0 + 16 * w < Lmax) {
            float facc[8] = {0.f, 0.f, 0.f, 0.f, 0.f, 0.f, 0.f, 0.f};
            for (int a0 = 0; a0 < A_; a0 += 8) {
                __half2 h0 = hz, h1 = hz, h2 = hz, h3 = hz;
#pragma unroll
                for (int aa = 0; aa < 8; aa++) {
                    int a = a0 + aa;
                    uint4 e = *reinterpret_cast<uint4*>(&ea2[a * 64 + kq * 4]);
                    __half2 qh = u2h2(qa2[q * QA2STR + a]);
                    __half2 v2 = u2h2(vs2[a]);
                    h0 = __hfma2(v2, tanh2(__hadd2(qh, u2h2(e.x))), h0);
                    h1 = __hfma2(v2, tanh2(__hadd2(qh, u2h2(e.y))), h1);
                    h2 = __hfma2(v2, tanh2(__hadd2(qh, u2h2(e.z))), h2);
                    h3 = __hfma2(v2, tanh2(__hadd2(qh, u2h2(e.w))), h3);
                }
                float2 t0 = __half22float2(h0), t1 = __half22float2(h1);
                float2 t2 = __half22float2(h2), t3 = __half22float2(h3);
                facc[0] += t0.x; facc[1] += t0.y; facc[2] += t1.x; facc[3] += t1.y;
                facc[4] += t2.x; facc[5] += t2.y; facc[6] += t3.x; facc[7] += t3.y;
            }

            float sl = 0.f;
            __half2 o[4];
#pragma unroll
            for (int j = 0; j < 4; j++) {
                float w0 = (kb + 2 * j     < Lq) ? __expf(facc[2 * j])     : 0.f;
                float w1 = (kb + 2 * j + 1 < Lq) ? __expf(facc[2 * j + 1]) : 0.f;
                sl += w0 + w1;
                o[j] = __floats2half2_rn(w0, w1);
            }
            *reinterpret_cast<uint4*>(&g_wexp_h[wrow + kb]) = *reinterpret_cast<uint4*>(o);
            atomicAdd(&sums[q], sl);
        } else {
            uint4 z = {0u, 0u, 0u, 0u};
            *reinterpret_cast<uint4*>(&g_wexp_h[wrow + kb]) = z;
        }
    }
    __syncthreads();
    if (tid < SQ) g_rowsum[(q0 + tid) * B_ + b] = sums[tid];
}

// ---------------- normalize + transpose (b,q,k) -> weights (q,k,b) -------------
__global__ void __launch_bounds__(256) norm_transpose_kernel(float* __restrict__ wout)
{
    __shared__ float tile[32][33];
    __shared__ float inv_s[32];
    int tid = threadIdx.x;
    int q = blockIdx.y;
    int k0 = blockIdx.x * 32;
    int tx = tid & 31;
    int ty = tid >> 5;
    int Lq = max(1, q - 1);
    if (tid < 32) inv_s[tid] = 1.f / g_rowsum[q * B_ + tid];
#pragma unroll
    for (int i = 0; i < 4; i++) {
        int bb = ty + i * 8;
        tile[bb][tx] = __half2float(g_wexp_h[((size_t)bb * S_ + q) * S_ + k0 + tx]);
    }
    __syncthreads();
#pragma unroll
    for (int i = 0; i < 4; i++) {
        int kk = ty + i * 8;
        float val = (k0 + kk < Lq) ? tile[tx][kk] * inv_s[tx] : 0.f;
        wout[((size_t)q * S_ + k0 + kk) * B_ + tx] = val;
    }
}

// ---------------- launch --------------------------------------------------------
extern "C" void kernel_launch(void* const* d_in, const int* in_sizes, int n_in,
                              void* d_out, int out_size)
{
    const float* outs  = (const float*)d_in[0];
    const float* emb   = (const float*)d_in[1];
    const float* W_enc = (const float*)d_in[2];
    const float* b_enc = (const float*)d_in[3];
    const float* W_dec = (const float*)d_in[4];
    const float* b_dec = (const float*)d_in[5];
    const float* v     = (const float*)d_in[6];
    const float* W_h2h = (const float*)d_in[7];
    const float* b_h2h = (const float*)d_in[8];
    const float* W_e2h = (const float*)d_in[9];
    const float* b_e2h = (const float*)d_in[10];
    float* out = (float*)d_out;

    __half *p_outs_h, *p_emb_h, *p_wexp, *p_ctx, *p_Wh2h, *p_We2h;
    cudaGetSymbolAddress((void**)&p_outs_h, g_outs_h);
    cudaGetSymbolAddress((void**)&p_emb_h, g_emb_h);
    cudaGetSymbolAddress((void**)&p_Wh2h, g_Wh2h_h);
    cudaGetSymbolAddress((void**)&p_We2h, g_We2h_h);
    cudaGetSymbolAddress((void**)&p_wexp, g_wexp_h);
    cudaGetSymbolAddress((void**)&p_ctx, g_context_h);

    const int SMEM0 = STG * (ASZ + B0SZ) * 2;   // 61440 B
    const int SMEM1 = STG * (ASZ + B1SZ) * 2;   // 56832 B
    cudaFuncSetAttribute(hgemm_proj2, cudaFuncAttributeMaxDynamicSharedMemorySize, SMEM0);
    cudaFuncSetAttribute(hgemm<1>, cudaFuncAttributeMaxDynamicSharedMemorySize, SMEM1);
    cudaFuncSetAttribute(hgemm<2>, cudaFuncAttributeMaxDynamicSharedMemorySize, SMEM0);
    cudaFuncSetAttribute(score_kernel, cudaFuncAttributeMaxDynamicSharedMemorySize, SCORE_SMEM);

    const size_t OUT1 = (size_t)S_ * B_ * H_;
    const size_t WSZ  = (size_t)S_ * S_ * B_;
    bool hasW = ((size_t)out_size >= OUT1 + WSZ);

    // 0. all fp32->fp16 conversions in one launch
    const int FGROUPS = 2 * BIGN8 + WN0 + WN1 + WN2 + WN3;   // 4,292,608
    f2h_all_kernel<<<FGROUPS / 256, 256>>>(outs, emb, W_enc, W_dec, W_h2h, W_e2h);

    // 1. both projections in one launch
    hgemm_proj2<<<dim3((S_ * B_) / BM, A_ / BN, 2), 256, SMEM0>>>(b_enc, b_dec);

    // 2. scores + exp + rowsums (pure MUFU — at hardware floor)
    score_kernel<<<dim3(S_ / SQ, B_), 256, SCORE_SMEM>>>(v);

    // 3. normalized weights output (q,k,b)
    if (hasW)
        norm_transpose_kernel<<<dim3(S_ / 32, S_), 256>>>(out + OUT1);

    // 4. context (triangular K, fused 1/rowsum, half out)
    hgemm<1><<<dim3(S_ / BM, E_ / BN, B_), 256, SMEM1>>>(
        p_wexp, p_emb_h, nullptr, nullptr, nullptr, nullptr, p_ctx, E_, S_, 0);

    // 5. output = outs@W_h2h^T + ctx@W_e2h^T + biases (fused dual-K) — ncu target
    hgemm<2><<<dim3((S_ * B_) / BM, H_ / BN), 256, SMEM0>>>(
        p_outs_h, p_Wh2h, p_ctx, p_We2h, b_h2h, b_e2h, out, H_, 1024, 0);
}

// round 16
// speedup vs baseline: 1.1967x; 1.0177x over previous
#include <cuda_runtime.h>
#include <cuda_fp16.h>
#include <cstdint>

#define S_ 1024
#define B_ 32
#define H_ 512
#define E_ 512
#define A_ 256

// ---------------- device scratch ------------------------------------------------
__device__ __half g_outs_h[(size_t)S_ * B_ * H_];
__device__ __half g_emb_h[(size_t)S_ * B_ * E_];
__device__ __half g_Wenc_h[A_ * E_];
__device__ __half g_Wdec_h[A_ * H_];
__device__ __half g_Wh2h_h[H_ * H_];
__device__ __half g_We2h_h[H_ * E_];
__device__ __half g_emb_att_h[(size_t)S_ * B_ * A_];   // [k*B+b][a]
__device__ __half g_q_att_h[(size_t)S_ * B_ * A_];     // [q*B+b][a]
__device__ __half g_wexp_h[(size_t)B_ * S_ * S_];      // [b][q][k]
__device__ __half g_context_h[(size_t)S_ * B_ * E_];   // [q*B+b][e]
__device__ float  g_rowsum[S_ * B_];                   // [q*B+b]

// ---------------- small helpers -------------------------------------------------
__device__ __forceinline__ __half2 u2h2(uint32_t u) { return *reinterpret_cast<__half2*>(&u); }
__device__ __forceinline__ uint32_t h22u(__half2 h) { return *reinterpret_cast<uint32_t*>(&h); }
__device__ __forceinline__ __half2 tanh2(__half2 x) {
    uint32_t u = h22u(x);
    asm("tanh.approx.f16x2 %0, %0;" : "+r"(u));
    return u2h2(u);
}
__device__ __forceinline__ void cpa16(uint32_t s, const void* g) {
    asm volatile("cp.async.cg.shared.global [%0], [%1], 16;" :: "r"(s), "l"(g));
}
#define CP_COMMIT() asm volatile("cp.async.commit_group;" ::: "memory")
#define CP_WAIT1()  asm volatile("cp.async.wait_group 1;" ::: "memory")

__device__ __forceinline__ void ldsm4(uint32_t& r0, uint32_t& r1, uint32_t& r2, uint32_t& r3, uint32_t a) {
    asm volatile("ldmatrix.sync.aligned.m8n8.x4.shared.b16 {%0,%1,%2,%3},[%4];"
                 : "=r"(r0), "=r"(r1), "=r"(r2), "=r"(r3) : "r"(a));
}
__device__ __forceinline__ void ldsm4t(uint32_t& r0, uint32_t& r1, uint32_t& r2, uint32_t& r3, uint32_t a) {
    asm volatile("ldmatrix.sync.aligned.m8n8.x4.trans.shared.b16 {%0,%1,%2,%3},[%4];"
                 : "=r"(r0), "=r"(r1), "=r"(r2), "=r"(r3) : "r"(a));
}
__device__ __forceinline__ void mma16816(float* d, const uint32_t* a, const uint32_t* b) {
    asm volatile("mma.sync.aligned.m16n8k16.row.col.f32.f16.f16.f32 "
                 "{%0,%1,%2,%3},{%4,%5,%6,%7},{%8,%9},{%0,%1,%2,%3};"
                 : "+f"(d[0]), "+f"(d[1]), "+f"(d[2]), "+f"(d[3])
                 : "r"(a[0]), "r"(a[1]), "r"(a[2]), "r"(a[3]), "r"(b[0]), "r"(b[1]));
}

// ---------------- convert ALL fp32 inputs -> fp16 in ONE launch ------------------
#define BIGN8 ((int)((size_t)S_ * B_ * H_ / 8))
#define WN0 (A_ * E_ / 8)
#define WN1 (A_ * H_ / 8)
#define WN2 (H_ * H_ / 8)
#define WN3 (H_ * E_ / 8)
__global__ void __launch_bounds__(256) f2h_all_kernel(
    const float* __restrict__ outs, const float* __restrict__ emb,
    const float* __restrict__ w0, const float* __restrict__ w1,
    const float* __restrict__ w2, const float* __restrict__ w3)
{
    int i = blockIdx.x * blockDim.x + threadIdx.x;
    const float* src; __half* dst; int loc;
    if (i < BIGN8)            { src = outs; dst = g_outs_h; loc = i; }
    else if (i < 2 * BIGN8)   { src = emb;  dst = g_emb_h;  loc = i - BIGN8; }
    else {
        int j = i - 2 * BIGN8;
        if (j < WN0)                    { src = w0; dst = g_Wenc_h; loc = j; }
        else if (j < WN0 + WN1)         { src = w1; dst = g_Wdec_h; loc = j - WN0; }
        else if (j < WN0 + WN1 + WN2)   { src = w2; dst = g_Wh2h_h; loc = j - WN0 - WN1; }
        else                            { src = w3; dst = g_We2h_h; loc = j - WN0 - WN1 - WN2; }
    }
    float4 f0 = reinterpret_cast<const float4*>(src)[loc * 2];
    float4 f1 = reinterpret_cast<const float4*>(src)[loc * 2 + 1];
    __half2 h[4] = { __floats2half2_rn(f0.x, f0.y), __floats2half2_rn(f0.z, f0.w),
                     __floats2half2_rn(f1.x, f1.y), __floats2half2_rn(f1.z, f1.w) };
    reinterpret_cast<uint4*>(dst)[loc] = *reinterpret_cast<uint4*>(h);
}

// ---------------- fp16 tensor-core GEMM body (BN=128, BK=32, STG=3) -------------
// MODE 0: C(half)[M,N] = A@W^T + bias1 ; optional row remap on A.
// MODE 1: context per b: Chalf[(m*B+b)*E+n] = (1/rowsum)*sum_k wexp_h[b][m][k]*emb_h[(k*B+b)*E+n]
// MODE 2: Cfloat[M,N] = A@W1^T + A2@W2^T + bias1 + bias2 (K=1024 split at 512)
#define BM 128
#define BN 128
#define BK 32
#define STG 3
#define ASTR 40
#define B1STR 136
#define ASZ  (BM * ASTR)
#define B0SZ (BN * ASTR)
#define B1SZ (BK * B1STR)

template<int MODE>
__device__ __forceinline__ void hgemm_body(
    const __half* __restrict__ A, const __half* __restrict__ Bm,
    const __half* __restrict__ A2, const __half* __restrict__ Bm2,
    const float* __restrict__ bias1, const float* __restrict__ bias2,
    void* __restrict__ Cv, int N, int K, int remap,
    int m0, int n0, int b, __half* sh)
{
    const int BSZ = (MODE == 1) ? B1SZ : B0SZ;
    __half* Asm = sh;
    __half* Bsm = sh + STG * ASZ;

    int tid = threadIdx.x;
    const __half* Ap = (MODE == 1) ? (A + (size_t)b * S_ * S_) : A;
    const int KA = (MODE == 1) ? S_ : ((MODE == 2) ? 512 : K);
    const int KB = (MODE == 2) ? 512 : K;

    int wid = tid >> 5, lane = tid & 31;
    int wm = (wid >> 2) * 64, wn = (wid & 3) * 32;

    int Kr = K;
    if (MODE == 1) { int Lmax = max(1, m0 + BM - 2); Kr = min(K, (Lmax + 31) & ~31); }
    int niter = Kr / BK;

    int arow = tid >> 2, ak8 = (tid & 3) * 8;
    int b1row = tid >> 4, b1n8 = (tid & 15) * 8;

    auto copy_stage = [&](int s, int k0) {
        __half* Ad = Asm + s * ASZ;
        __half* Bd = Bsm + s * BSZ;
        const __half* Asrc = Ap; const __half* Bsrc = Bm; int kk = k0;
        if (MODE == 2 && k0 >= 512) { Asrc = A2; Bsrc = Bm2; kk = k0 - 512; }
#pragma unroll
        for (int j = 0; j < 2; j++) {
            int row = arow + j * 64;
            int gr = m0 + row;
            int sr = (MODE == 0 && remap) ? (gr >= B_ ? gr - B_ : gr) : gr;
            cpa16((uint32_t)__cvta_generic_to_shared(Ad + row * ASTR + ak8),
                  Asrc + (size_t)sr * KA + kk + ak8);
        }
        if (MODE == 1) {
#pragma unroll
            for (int j = 0; j < 2; j++) {
                int r = b1row + j * 16;
                cpa16((uint32_t)__cvta_generic_to_shared(Bd + r * B1STR + b1n8),
                      Bm + ((size_t)(k0 + r) * B_ + b) * E_ + n0 + b1n8);
            }
        } else {
#pragma unroll
            for (int j = 0; j < 2; j++) {
                int row = arow + j * 64;
                cpa16((uint32_t)__cvta_generic_to_shared(Bd + row * ASTR + ak8),
                      Bsrc + (size_t)(n0 + row) * KB + kk + ak8);
            }
        }
    };

    uint32_t a_off[4], b_off[2];
    {
        int r = lane & 15, koff = (lane >> 4) * 8;
#pragma unroll
        for (int mt = 0; mt < 4; mt++) {
            int row = wm + mt * 16 + r;
            a_off[mt] = (uint32_t)__cvta_generic_to_shared(Asm + row * ASTR + koff);
        }
        if (MODE == 1) {
            int k = ((lane >> 3) & 1) * 8 + (lane & 7);
#pragma unroll
            for (int p = 0; p < 2; p++) {
                int n = wn + p * 16 + (lane >> 4) * 8;
                b_off[p] = (uint32_t)__cvta_generic_to_shared(Bsm + k * B1STR + n);
            }
        } else {
            int koffb = ((lane >> 3) & 1) * 8;
            int nb = (lane >> 4) * 8 + (lane & 7);
#pragma unroll
            for (int p = 0; p < 2; p++) {
                int n = wn + p * 16 + nb;
                b_off[p] = (uint32_t)__cvta_generic_to_shared(Bsm + n * ASTR + koffb);
            }
        }
    }

    float acc[4][4][4];
#pragma unroll
    for (int i = 0; i < 4; i++)
#pragma unroll
        for (int j = 0; j < 4; j++)
#pragma unroll
            for (int r = 0; r < 4; r++) acc[i][j][r] = 0.f;

#pragma unroll
    for (int s = 0; s < STG - 1; s++) {
        if (s < niter) copy_stage(s, s * BK);
        CP_COMMIT();
    }

    for (int it = 0; it < niter; it++) {
        CP_WAIT1();
        __syncthreads();
        if (it + STG - 1 < niter) copy_stage((it + STG - 1) % STG, (it + STG - 1) * BK);
        CP_COMMIT();

        uint32_t ab = (uint32_t)((it % STG) * ASZ * 2);
        uint32_t bb = (uint32_t)((it % STG) * BSZ * 2);

#pragma unroll
        for (int s = 0; s < 2; s++) {
            uint32_t astep = ab + s * 32;
            uint32_t bstep = (MODE == 1) ? (bb + s * 16 * B1STR * 2) : (bb + s * 32);
            uint32_t af[4][4], bf[2][4];
#pragma unroll
            for (int mt = 0; mt < 4; mt++)
                ldsm4(af[mt][0], af[mt][1], af[mt][2], af[mt][3], a_off[mt] + astep);
#pragma unroll
            for (int p = 0; p < 2; p++) {
                if (MODE == 1) ldsm4t(bf[p][0], bf[p][1], bf[p][2], bf[p][3], b_off[p] + bstep);
                else           ldsm4 (bf[p][0], bf[p][1], bf[p][2], bf[p][3], b_off[p] + bstep);
            }
#pragma unroll
            for (int mt = 0; mt < 4; mt++)
#pragma unroll
                for (int nt = 0; nt < 4; nt++)
                    mma16816(acc[mt][nt], af[mt], &bf[nt >> 1][(nt & 1) * 2]);
        }
        // no trailing sync: next iter's leading barrier protects the stage the
        // next copy overwrites ((it+2)%3 == (it-1)%3, released by that barrier).
    }

    int lr = lane >> 2, lc = lane & 3;
#pragma unroll
    for (int mt = 0; mt < 4; mt++) {
        int mA = m0 + wm + mt * 16 + lr;
        float sc0 = 1.f, sc1 = 1.f;
        if (MODE == 1) {
            sc0 = 1.f / g_rowsum[mA * B_ + b];
            sc1 = 1.f / g_rowsum[(mA + 8) * B_ + b];
        }
#pragma unroll
        for (int nt = 0; nt < 4; nt++) {
            int n = n0 + wn + nt * 8 + lc * 2;
            float* d = acc[mt][nt];
            if (MODE == 0) {
                float a0 = bias1 ? bias1[n] : 0.f, a1 = bias1 ? bias1[n + 1] : 0.f;
                __half* C = (__half*)Cv;
                *reinterpret_cast<__half2*>(&C[(size_t)mA * N + n]) =
                    __floats2half2_rn(d[0] + a0, d[1] + a1);
                *reinterpret_cast<__half2*>(&C[(size_t)(mA + 8) * N + n]) =
                    __floats2half2_rn(d[2] + a0, d[3] + a1);
            } else if (MODE == 1) {
                __half* C = (__half*)Cv;
                *reinterpret_cast<__half2*>(&C[((size_t)mA * B_ + b) * E_ + n]) =
                    __floats2half2_rn(d[0] * sc0, d[1] * sc0);
                *reinterpret_cast<__half2*>(&C[((size_t)(mA + 8) * B_ + b) * E_ + n]) =
                    __floats2half2_rn(d[2] * sc1, d[3] * sc1);
            } else {
                float a0 = bias1[n] + bias2[n], a1 = bias1[n + 1] + bias2[n + 1];
                float* C = (float*)Cv;
                float2 v0 = {d[0] + a0, d[1] + a1};
                float2 v1 = {d[2] + a0, d[3] + a1};
                *reinterpret_cast<float2*>(&C[(size_t)mA * N + n]) = v0;
                *reinterpret_cast<float2*>(&C[(size_t)(mA + 8) * N + n]) = v1;
            }
        }
    }
}

template<int MODE>
__global__ void __launch_bounds__(256, 2) hgemm(
    const __half* __restrict__ A, const __half* __restrict__ Bm,
    const __half* __restrict__ A2, const __half* __restrict__ Bm2,
    const float* __restrict__ bias1, const float* __restrict__ bias2,
    void* __restrict__ Cv, int N, int K, int remap)
{
    extern __shared__ __half sh[];
    hgemm_body<MODE>(A, Bm, A2, Bm2, bias1, bias2, Cv, N, K, remap,
                     blockIdx.x * BM, blockIdx.y * BN, blockIdx.z, sh);
}

// both projections in one launch: z=0 -> emb_att, z=1 -> q_att (remapped rows)
__global__ void __launch_bounds__(256, 2) hgemm_proj2(
    const float* __restrict__ b_enc, const float* __restrict__ b_dec)
{
    extern __shared__ __half sh[];
    if (blockIdx.z == 0)
        hgemm_body<0>(g_emb_h, g_Wenc_h, nullptr, nullptr, b_enc, nullptr,
                      g_emb_att_h, A_, E_, 0, blockIdx.x * BM, blockIdx.y * BN, 0, sh);
    else
        hgemm_body<0>(g_outs_h, g_Wdec_h, nullptr, nullptr, b_dec, nullptr,
                      g_q_att_h, A_, H_, 1, blockIdx.x * BM, blockIdx.y * BN, 0, sh);
}

// ---------------- scores: pure-MUFU tanh2, heavy-tiles-first scheduling ---------
#define SQ 16
#define QA2STR 257
#define SCORE_W (16384 + SQ * QA2STR + 256 + 16)
#define SCORE_SMEM (SCORE_W * 4)

__global__ void __launch_bounds__(256) score_kernel(const float* __restrict__ v)
{
    extern __shared__ uint32_t sw[];
    uint32_t* ea2 = sw;                        // [256 a][64 k2] half2
    uint32_t* qa2 = sw + 16384;                // [16 q][257] dup-half2
    uint32_t* vs2 = sw + 16384 + SQ * QA2STR;  // [256] dup-half2
    float* sums = (float*)(vs2 + 256);         // [16]

    int tid = threadIdx.x;
    // heavy-first: large q0 (most keys) scheduled at low blockIdx.x
    int q0 = ((int)gridDim.x - 1 - (int)blockIdx.x) * SQ;
    int b = blockIdx.y;
    int q = tid & 15, kq = tid >> 4, w = tid >> 5;
    int qg = q0 + q;
    int Lq = max(1, qg - 1);

    vs2[tid] = h22u(__floats2half2_rn(v[tid], v[tid]));
    if (tid < SQ) sums[tid] = 0.f;
#pragma unroll
    for (int it = 0; it < 2; it++) {
        int lin = tid + it * 256;
        int qq = lin >> 5, a8 = lin & 31;
        uint4 u = *reinterpret_cast<const uint4*>(
            g_q_att_h + ((size_t)(q0 + qq) * B_ + b) * A_ + a8 * 8);
        __half h[8]; *reinterpret_cast<uint4*>(h) = u;
#pragma unroll
        for (int i = 0; i < 8; i++)
            qa2[qq * QA2STR + a8 * 8 + i] = h22u(__half2half2(h[i]));
    }

    int Lmax = max(1, q0 + SQ - 2);
    size_t wrow = ((size_t)b * S_ + qg) * S_;
    const __half2 hz = __floats2half2_rn(0.f, 0.f);

    for (int k0 = 0; k0 < Lmax; k0 += 128) {
        __syncthreads();
#pragma unroll
        for (int it = 0; it < 8; it++) {
            int lin = tid + it * 256;
            int k2 = lin & 63, a8 = lin >> 6;
            const __half* p = g_emb_att_h + ((size_t)(k0 + 2 * k2) * B_ + b) * A_ + a8 * 8;
            uint4 u0 = *reinterpret_cast<const uint4*>(p);
            uint4 u1 = *reinterpret_cast<const uint4*>(p + (size_t)B_ * A_);
            __half h0[8], h1[8];
            *reinterpret_cast<uint4*>(h0) = u0;
            *reinterpret_cast<uint4*>(h1) = u1;
#pragma unroll
            for (int i = 0; i < 8; i++)
                ea2[(a8 * 8 + i) * 64 + k2] = h22u(__halves2half2(h0[i], h1[i]));
        }
        __syncthreads();

        int kb = k0 + kq * 8;
        if (k0 + 16 * w < Lmax) {
            float facc[8] = {0.f, 0.f, 0.f, 0.f, 0.f, 0.f, 0.f, 0.f};
            for (int a0 = 0; a0 < A_; a0 += 8) {
                __half2 h0 = hz, h1 = hz, h2 = hz, h3 = hz;
#pragma unroll
                for (int aa = 0; aa < 8; aa++) {
                    int a = a0 + aa;
                    uint4 e = *reinterpret_cast<uint4*>(&ea2[a * 64 + kq * 4]);
                    __half2 qh = u2h2(qa2[q * QA2STR + a]);
                    __half2 v2 = u2h2(vs2[a]);
                    h0 = __hfma2(v2, tanh2(__hadd2(qh, u2h2(e.x))), h0);
                    h1 = __hfma2(v2, tanh2(__hadd2(qh, u2h2(e.y))), h1);
                    h2 = __hfma2(v2, tanh2(__hadd2(qh, u2h2(e.z))), h2);
                    h3 = __hfma2(v2, tanh2(__hadd2(qh, u2h2(e.w))), h3);
                }
                float2 t0 = __half22float2(h0), t1 = __half22float2(h1);
                float2 t2 = __half22float2(h2), t3 = __half22float2(h3);
                facc[0] += t0.x; facc[1] += t0.y; facc[2] += t1.x; facc[3] += t1.y;
                facc[4] += t2.x; facc[5] += t2.y; facc[6] += t3.x; facc[7] += t3.y;
            }

            float sl = 0.f;
            __half2 o[4];
#pragma unroll
            for (int j = 0; j < 4; j++) {
                float w0 = (kb + 2 * j     < Lq) ? __expf(facc[2 * j])     : 0.f;
                float w1 = (kb + 2 * j + 1 < Lq) ? __expf(facc[2 * j + 1]) : 0.f;
                sl += w0 + w1;
                o[j] = __floats2half2_rn(w0, w1);
            }
            *reinterpret_cast<uint4*>(&g_wexp_h[wrow + kb]) = *reinterpret_cast<uint4*>(o);
            atomicAdd(&sums[q], sl);
        } else {
            uint4 z = {0u, 0u, 0u, 0u};
            *reinterpret_cast<uint4*>(&g_wexp_h[wrow + kb]) = z;
        }
    }
    __syncthreads();
    if (tid < SQ) g_rowsum[(q0 + tid) * B_ + b] = sums[tid];
}

// ---------------- normalize + transpose (b,q,k) -> weights (q,k,b) -------------
// (round-13 proven version)
__global__ void __launch_bounds__(256) norm_transpose_kernel(float* __restrict__ wout)
{
    __shared__ float tile[32][33];
    __shared__ float inv_s[32];
    int tid = threadIdx.x;
    int q = blockIdx.y;
    int k0 = blockIdx.x * 32;
    int tx = tid & 31;
    int ty = tid >> 5;
    int Lq = max(1, q - 1);
    if (tid < 32) inv_s[tid] = 1.f / g_rowsum[q * B_ + tid];
#pragma unroll
    for (int i = 0; i < 4; i++) {
        int bb = ty + i * 8;
        tile[bb][tx] = __half2float(g_wexp_h[((size_t)bb * S_ + q) * S_ + k0 + tx]);
    }
    __syncthreads();
#pragma unroll
    for (int i = 0; i < 4; i++) {
        int kk = ty + i * 8;
        float val = (k0 + kk < Lq) ? tile[tx][kk] * inv_s[tx] : 0.f;
        wout[((size_t)q * S_ + k0 + kk) * B_ + tx] = val;
    }
}

// ---------------- launch --------------------------------------------------------
extern "C" void kernel_launch(void* const* d_in, const int* in_sizes, int n_in,
                              void* d_out, int out_size)
{
    const float* outs  = (const float*)d_in[0];
    const float* emb   = (const float*)d_in[1];
    const float* W_enc = (const float*)d_in[2];
    const float* b_enc = (const float*)d_in[3];
    const float* W_dec = (const float*)d_in[4];
    const float* b_dec = (const float*)d_in[5];
    const float* v     = (const float*)d_in[6];
    const float* W_h2h = (const float*)d_in[7];
    const float* b_h2h = (const float*)d_in[8];
    const float* W_e2h = (const float*)d_in[9];
    const float* b_e2h = (const float*)d_in[10];
    float* out = (float*)d_out;

    __half *p_outs_h, *p_emb_h, *p_wexp, *p_ctx, *p_Wh2h, *p_We2h;
    cudaGetSymbolAddress((void**)&p_outs_h, g_outs_h);
    cudaGetSymbolAddress((void**)&p_emb_h, g_emb_h);
    cudaGetSymbolAddress((void**)&p_Wh2h, g_Wh2h_h);
    cudaGetSymbolAddress((void**)&p_We2h, g_We2h_h);
    cudaGetSymbolAddress((void**)&p_wexp, g_wexp_h);
    cudaGetSymbolAddress((void**)&p_ctx, g_context_h);

    const int SMEM0 = STG * (ASZ + B0SZ) * 2;   // 61440 B
    const int SMEM1 = STG * (ASZ + B1SZ) * 2;   // 56832 B
    cudaFuncSetAttribute(hgemm_proj2, cudaFuncAttributeMaxDynamicSharedMemorySize, SMEM0);
    cudaFuncSetAttribute(hgemm<1>, cudaFuncAttributeMaxDynamicSharedMemorySize, SMEM1);
    cudaFuncSetAttribute(hgemm<2>, cudaFuncAttributeMaxDynamicSharedMemorySize, SMEM0);
    cudaFuncSetAttribute(score_kernel, cudaFuncAttributeMaxDynamicSharedMemorySize, SCORE_SMEM);

    const size_t OUT1 = (size_t)S_ * B_ * H_;
    const size_t WSZ  = (size_t)S_ * S_ * B_;
    bool hasW = ((size_t)out_size >= OUT1 + WSZ);

    // 0. all fp32->fp16 conversions in one launch
    const int FGROUPS = 2 * BIGN8 + WN0 + WN1 + WN2 + WN3;
    f2h_all_kernel<<<FGROUPS / 256, 256>>>(outs, emb, W_enc, W_dec, W_h2h, W_e2h);

    // 1. both projections in one launch
    hgemm_proj2<<<dim3((S_ * B_) / BM, A_ / BN, 2), 256, SMEM0>>>(b_enc, b_dec);

    // 2. scores + exp + rowsums (pure MUFU, heavy tiles first)
    score_kernel<<<dim3(S_ / SQ, B_), 256, SCORE_SMEM>>>(v);

    // 3. normalized weights output (q,k,b)
    if (hasW)
        norm_transpose_kernel<<<dim3(S_ / 32, S_), 256>>>(out + OUT1);

    // 4. context (triangular K, fused 1/rowsum, half out)
    hgemm<1><<<dim3(S_ / BM, E_ / BN, B_), 256, SMEM1>>>(
        p_wexp, p_emb_h, nullptr, nullptr, nullptr, nullptr, p_ctx, E_, S_, 0);

    // 5. output = outs@W_h2h^T + ctx@W_e2h^T + biases (fused dual-K)
    hgemm<2><<<dim3((S_ * B_) / BM, H_ / BN), 256, SMEM0>>>(
        p_outs_h, p_Wh2h, p_ctx, p_We2h, b_h2h, b_e2h, out, H_, 1024, 0);
}

// round 17
// speedup vs baseline: 1.2083x; 1.0096x over previous
#include <cuda_runtime.h>
#include <cuda_fp16.h>
#include <cstdint>

#define S_ 1024
#define B_ 32
#define H_ 512
#define E_ 512
#define A_ 256

// ---------------- device scratch ------------------------------------------------
__device__ __half g_outs_h[(size_t)S_ * B_ * H_];
__device__ __half g_emb_h[(size_t)S_ * B_ * E_];
__device__ __half g_Wenc_h[A_ * E_];
__device__ __half g_Wdec_h[A_ * H_];
__device__ __half g_Wh2h_h[H_ * H_];
__device__ __half g_We2h_h[H_ * E_];
__device__ __half g_emb_att_h[(size_t)S_ * B_ * A_];   // [k*B+b][a]
__device__ __half g_q_att_h[(size_t)S_ * B_ * A_];     // [q*B+b][a]
__device__ __half g_wexp_h[(size_t)B_ * S_ * S_];      // [b][q][k]
__device__ __half g_context_h[(size_t)S_ * B_ * E_];   // [q*B+b][e]
__device__ float  g_rowsum[S_ * B_];                   // [q*B+b]

// ---------------- small helpers -------------------------------------------------
__device__ __forceinline__ __half2 u2h2(uint32_t u) { return *reinterpret_cast<__half2*>(&u); }
__device__ __forceinline__ uint32_t h22u(__half2 h) { return *reinterpret_cast<uint32_t*>(&h); }
__device__ __forceinline__ __half2 tanh2(__half2 x) {
    uint32_t u = h22u(x);
    asm("tanh.approx.f16x2 %0, %0;" : "+r"(u));
    return u2h2(u);
}
__device__ __forceinline__ void cpa16(uint32_t s, const void* g) {
    asm volatile("cp.async.cg.shared.global [%0], [%1], 16;" :: "r"(s), "l"(g));
}
#define CP_COMMIT() asm volatile("cp.async.commit_group;" ::: "memory")
#define CP_WAIT1()  asm volatile("cp.async.wait_group 1;" ::: "memory")

__device__ __forceinline__ void ldsm4(uint32_t& r0, uint32_t& r1, uint32_t& r2, uint32_t& r3, uint32_t a) {
    asm volatile("ldmatrix.sync.aligned.m8n8.x4.shared.b16 {%0,%1,%2,%3},[%4];"
                 : "=r"(r0), "=r"(r1), "=r"(r2), "=r"(r3) : "r"(a));
}
__device__ __forceinline__ void ldsm4t(uint32_t& r0, uint32_t& r1, uint32_t& r2, uint32_t& r3, uint32_t a) {
    asm volatile("ldmatrix.sync.aligned.m8n8.x4.trans.shared.b16 {%0,%1,%2,%3},[%4];"
                 : "=r"(r0), "=r"(r1), "=r"(r2), "=r"(r3) : "r"(a));
}
__device__ __forceinline__ void mma16816(float* d, const uint32_t* a, const uint32_t* b) {
    asm volatile("mma.sync.aligned.m16n8k16.row.col.f32.f16.f16.f32 "
                 "{%0,%1,%2,%3},{%4,%5,%6,%7},{%8,%9},{%0,%1,%2,%3};"
                 : "+f"(d[0]), "+f"(d[1]), "+f"(d[2]), "+f"(d[3])
                 : "r"(a[0]), "r"(a[1]), "r"(a[2]), "r"(a[3]), "r"(b[0]), "r"(b[1]));
}

// ---------------- convert ALL fp32 inputs -> fp16 in ONE launch ------------------
#define BIGN8 ((int)((size_t)S_ * B_ * H_ / 8))
#define WN0 (A_ * E_ / 8)
#define WN1 (A_ * H_ / 8)
#define WN2 (H_ * H_ / 8)
#define WN3 (H_ * E_ / 8)
__global__ void __launch_bounds__(256) f2h_all_kernel(
    const float* __restrict__ outs, const float* __restrict__ emb,
    const float* __restrict__ w0, const float* __restrict__ w1,
    const float* __restrict__ w2, const float* __restrict__ w3)
{
    int i = blockIdx.x * blockDim.x + threadIdx.x;
    const float* src; __half* dst; int loc;
    if (i < BIGN8)            { src = outs; dst = g_outs_h; loc = i; }
    else if (i < 2 * BIGN8)   { src = emb;  dst = g_emb_h;  loc = i - BIGN8; }
    else {
        int j = i - 2 * BIGN8;
        if (j < WN0)                    { src = w0; dst = g_Wenc_h; loc = j; }
        else if (j < WN0 + WN1)         { src = w1; dst = g_Wdec_h; loc = j - WN0; }
        else if (j < WN0 + WN1 + WN2)   { src = w2; dst = g_Wh2h_h; loc = j - WN0 - WN1; }
        else                            { src = w3; dst = g_We2h_h; loc = j - WN0 - WN1 - WN2; }
    }
    float4 f0 = reinterpret_cast<const float4*>(src)[loc * 2];
    float4 f1 = reinterpret_cast<const float4*>(src)[loc * 2 + 1];
    __half2 h[4] = { __floats2half2_rn(f0.x, f0.y), __floats2half2_rn(f0.z, f0.w),
                     __floats2half2_rn(f1.x, f1.y), __floats2half2_rn(f1.z, f1.w) };
    reinterpret_cast<uint4*>(dst)[loc] = *reinterpret_cast<uint4*>(h);
}

// ---------------- fp16 tensor-core GEMM body (BN=128, BK=32, STG=3) -------------
// MODE 0: C(half)[M,N] = A@W^T + bias1 ; optional row remap on A.
// MODE 1: context per b: Chalf[(m*B+b)*E+n] = (1/rowsum)*sum_k wexp_h[b][m][k]*emb_h[(k*B+b)*E+n]
// MODE 2: Cfloat[M,N] = A@W1^T + A2@W2^T + bias1 + bias2 (K=1024 split at 512)
#define BM 128
#define BN 128
#define BK 32
#define STG 3
#define ASTR 40
#define B1STR 136
#define ASZ  (BM * ASTR)
#define B0SZ (BN * ASTR)
#define B1SZ (BK * B1STR)

template<int MODE>
__device__ __forceinline__ void hgemm_body(
    const __half* __restrict__ A, const __half* __restrict__ Bm,
    const __half* __restrict__ A2, const __half* __restrict__ Bm2,
    const float* __restrict__ bias1, const float* __restrict__ bias2,
    void* __restrict__ Cv, int N, int K, int remap,
    int m0, int n0, int b, __half* sh)
{
    const int BSZ = (MODE == 1) ? B1SZ : B0SZ;
    __half* Asm = sh;
    __half* Bsm = sh + STG * ASZ;

    int tid = threadIdx.x;
    const __half* Ap = (MODE == 1) ? (A + (size_t)b * S_ * S_) : A;
    const int KA = (MODE == 1) ? S_ : ((MODE == 2) ? 512 : K);
    const int KB = (MODE == 2) ? 512 : K;

    int wid = tid >> 5, lane = tid & 31;
    int wm = (wid >> 2) * 64, wn = (wid & 3) * 32;

    int Kr = K;
    if (MODE == 1) { int Lmax = max(1, m0 + BM - 2); Kr = min(K, (Lmax + 31) & ~31); }
    int niter = Kr / BK;

    int arow = tid >> 2, ak8 = (tid & 3) * 8;
    int b1row = tid >> 4, b1n8 = (tid & 15) * 8;

    auto copy_stage = [&](int s, int k0) {
        __half* Ad = Asm + s * ASZ;
        __half* Bd = Bsm + s * BSZ;
        const __half* Asrc = Ap; const __half* Bsrc = Bm; int kk = k0;
        if (MODE == 2 && k0 >= 512) { Asrc = A2; Bsrc = Bm2; kk = k0 - 512; }
#pragma unroll
        for (int j = 0; j < 2; j++) {
            int row = arow + j * 64;
            int gr = m0 + row;
            int sr = (MODE == 0 && remap) ? (gr >= B_ ? gr - B_ : gr) : gr;
            cpa16((uint32_t)__cvta_generic_to_shared(Ad + row * ASTR + ak8),
                  Asrc + (size_t)sr * KA + kk + ak8);
        }
        if (MODE == 1) {
#pragma unroll
            for (int j = 0; j < 2; j++) {
                int r = b1row + j * 16;
                cpa16((uint32_t)__cvta_generic_to_shared(Bd + r * B1STR + b1n8),
                      Bm + ((size_t)(k0 + r) * B_ + b) * E_ + n0 + b1n8);
            }
        } else {
#pragma unroll
            for (int j = 0; j < 2; j++) {
                int row = arow + j * 64;
                cpa16((uint32_t)__cvta_generic_to_shared(Bd + row * ASTR + ak8),
                      Bsrc + (size_t)(n0 + row) * KB + kk + ak8);
            }
        }
    };

    uint32_t a_off[4], b_off[2];
    {
        int r = lane & 15, koff = (lane >> 4) * 8;
#pragma unroll
        for (int mt = 0; mt < 4; mt++) {
            int row = wm + mt * 16 + r;
            a_off[mt] = (uint32_t)__cvta_generic_to_shared(Asm + row * ASTR + koff);
        }
        if (MODE == 1) {
            int k = ((lane >> 3) & 1) * 8 + (lane & 7);
#pragma unroll
            for (int p = 0; p < 2; p++) {
                int n = wn + p * 16 + (lane >> 4) * 8;
                b_off[p] = (uint32_t)__cvta_generic_to_shared(Bsm + k * B1STR + n);
            }
        } else {
            int koffb = ((lane >> 3) & 1) * 8;
            int nb = (lane >> 4) * 8 + (lane & 7);
#pragma unroll
            for (int p = 0; p < 2; p++) {
                int n = wn + p * 16 + nb;
                b_off[p] = (uint32_t)__cvta_generic_to_shared(Bsm + n * ASTR + koffb);
            }
        }
    }

    float acc[4][4][4];
#pragma unroll
    for (int i = 0; i < 4; i++)
#pragma unroll
        for (int j = 0; j < 4; j++)
#pragma unroll
            for (int r = 0; r < 4; r++) acc[i][j][r] = 0.f;

#pragma unroll
    for (int s = 0; s < STG - 1; s++) {
        if (s < niter) copy_stage(s, s * BK);
        CP_COMMIT();
    }

    for (int it = 0; it < niter; it++) {
        CP_WAIT1();
        __syncthreads();
        if (it + STG - 1 < niter) copy_stage((it + STG - 1) % STG, (it + STG - 1) * BK);
        CP_COMMIT();

        uint32_t ab = (uint32_t)((it % STG) * ASZ * 2);
        uint32_t bb = (uint32_t)((it % STG) * BSZ * 2);

#pragma unroll
        for (int s = 0; s < 2; s++) {
            uint32_t astep = ab + s * 32;
            uint32_t bstep = (MODE == 1) ? (bb + s * 16 * B1STR * 2) : (bb + s * 32);
            uint32_t af[4][4], bf[2][4];
#pragma unroll
            for (int mt = 0; mt < 4; mt++)
                ldsm4(af[mt][0], af[mt][1], af[mt][2], af[mt][3], a_off[mt] + astep);
#pragma unroll
            for (int p = 0; p < 2; p++) {
                if (MODE == 1) ldsm4t(bf[p][0], bf[p][1], bf[p][2], bf[p][3], b_off[p] + bstep);
                else           ldsm4 (bf[p][0], bf[p][1], bf[p][2], bf[p][3], b_off[p] + bstep);
            }
#pragma unroll
            for (int mt = 0; mt < 4; mt++)
#pragma unroll
                for (int nt = 0; nt < 4; nt++)
                    mma16816(acc[mt][nt], af[mt], &bf[nt >> 1][(nt & 1) * 2]);
        }
        // no trailing sync: next iter's leading barrier protects the stage the
        // next copy overwrites ((it+2)%3 == (it-1)%3, released by that barrier).
    }

    int lr = lane >> 2, lc = lane & 3;
#pragma unroll
    for (int mt = 0; mt < 4; mt++) {
        int mA = m0 + wm + mt * 16 + lr;
        float sc0 = 1.f, sc1 = 1.f;
        if (MODE == 1) {
            sc0 = 1.f / g_rowsum[mA * B_ + b];
            sc1 = 1.f / g_rowsum[(mA + 8) * B_ + b];
        }
#pragma unroll
        for (int nt = 0; nt < 4; nt++) {
            int n = n0 + wn + nt * 8 + lc * 2;
            float* d = acc[mt][nt];
            if (MODE == 0) {
                float a0 = bias1 ? bias1[n] : 0.f, a1 = bias1 ? bias1[n + 1] : 0.f;
                __half* C = (__half*)Cv;
                *reinterpret_cast<__half2*>(&C[(size_t)mA * N + n]) =
                    __floats2half2_rn(d[0] + a0, d[1] + a1);
                *reinterpret_cast<__half2*>(&C[(size_t)(mA + 8) * N + n]) =
                    __floats2half2_rn(d[2] + a0, d[3] + a1);
            } else if (MODE == 1) {
                __half* C = (__half*)Cv;
                *reinterpret_cast<__half2*>(&C[((size_t)mA * B_ + b) * E_ + n]) =
                    __floats2half2_rn(d[0] * sc0, d[1] * sc0);
                *reinterpret_cast<__half2*>(&C[((size_t)(mA + 8) * B_ + b) * E_ + n]) =
                    __floats2half2_rn(d[2] * sc1, d[3] * sc1);
            } else {
                float a0 = bias1[n] + bias2[n], a1 = bias1[n + 1] + bias2[n + 1];
                float* C = (float*)Cv;
                float2 v0 = {d[0] + a0, d[1] + a1};
                float2 v1 = {d[2] + a0, d[3] + a1};
                *reinterpret_cast<float2*>(&C[(size_t)mA * N + n]) = v0;
                *reinterpret_cast<float2*>(&C[(size_t)(mA + 8) * N + n]) = v1;
            }
        }
    }
}

template<int MODE>
__global__ void __launch_bounds__(256, 2) hgemm(
    const __half* __restrict__ A, const __half* __restrict__ Bm,
    const __half* __restrict__ A2, const __half* __restrict__ Bm2,
    const float* __restrict__ bias1, const float* __restrict__ bias2,
    void* __restrict__ Cv, int N, int K, int remap)
{
    extern __shared__ __half sh[];
    // MODE 1 is triangular in m0: schedule heavy (large-m0) tiles first.
    int bx = (MODE == 1) ? ((int)gridDim.x - 1 - (int)blockIdx.x) : (int)blockIdx.x;
    hgemm_body<MODE>(A, Bm, A2, Bm2, bias1, bias2, Cv, N, K, remap,
                     bx * BM, blockIdx.y * BN, blockIdx.z, sh);
}

// both projections in one launch: z=0 -> emb_att, z=1 -> q_att (remapped rows)
__global__ void __launch_bounds__(256, 2) hgemm_proj2(
    const float* __restrict__ b_enc, const float* __restrict__ b_dec)
{
    extern __shared__ __half sh[];
    if (blockIdx.z == 0)
        hgemm_body<0>(g_emb_h, g_Wenc_h, nullptr, nullptr, b_enc, nullptr,
                      g_emb_att_h, A_, E_, 0, blockIdx.x * BM, blockIdx.y * BN, 0, sh);
    else
        hgemm_body<0>(g_outs_h, g_Wdec_h, nullptr, nullptr, b_dec, nullptr,
                      g_q_att_h, A_, H_, 1, blockIdx.x * BM, blockIdx.y * BN, 0, sh);
}

// ---------------- scores: pure-MUFU tanh2, heavy-tiles-first scheduling ---------
#define SQ 16
#define QA2STR 257
#define SCORE_W (16384 + SQ * QA2STR + 256 + 16)
#define SCORE_SMEM (SCORE_W * 4)

__global__ void __launch_bounds__(256) score_kernel(const float* __restrict__ v)
{
    extern __shared__ uint32_t sw[];
    uint32_t* ea2 = sw;                        // [256 a][64 k2] half2
    uint32_t* qa2 = sw + 16384;                // [16 q][257] dup-half2
    uint32_t* vs2 = sw + 16384 + SQ * QA2STR;  // [256] dup-half2
    float* sums = (float*)(vs2 + 256);         // [16]

    int tid = threadIdx.x;
    int q0 = ((int)gridDim.x - 1 - (int)blockIdx.x) * SQ;
    int b = blockIdx.y;
    int q = tid & 15, kq = tid >> 4, w = tid >> 5;
    int qg = q0 + q;
    int Lq = max(1, qg - 1);

    vs2[tid] = h22u(__floats2half2_rn(v[tid], v[tid]));
    if (tid < SQ) sums[tid] = 0.f;
#pragma unroll
    for (int it = 0; it < 2; it++) {
        int lin = tid + it * 256;
        int qq = lin >> 5, a8 = lin & 31;
        uint4 u = *reinterpret_cast<const uint4*>(
            g_q_att_h + ((size_t)(q0 + qq) * B_ + b) * A_ + a8 * 8);
        __half h[8]; *reinterpret_cast<uint4*>(h) = u;
#pragma unroll
        for (int i = 0; i < 8; i++)
            qa2[qq * QA2STR + a8 * 8 + i] = h22u(__half2half2(h[i]));
    }

    int Lmax = max(1, q0 + SQ - 2);
    size_t wrow = ((size_t)b * S_ + qg) * S_;
    const __half2 hz = __floats2half2_rn(0.f, 0.f);

    for (int k0 = 0; k0 < Lmax; k0 += 128) {
        __syncthreads();
#pragma unroll
        for (int it = 0; it < 8; it++) {
            int lin = tid + it * 256;
            int k2 = lin & 63, a8 = lin >> 6;
            const __half* p = g_emb_att_h + ((size_t)(k0 + 2 * k2) * B_ + b) * A_ + a8 * 8;
            uint4 u0 = *reinterpret_cast<const uint4*>(p);
            uint4 u1 = *reinterpret_cast<const uint4*>(p + (size_t)B_ * A_);
            __half h0[8], h1[8];
            *reinterpret_cast<uint4*>(h0) = u0;
            *reinterpret_cast<uint4*>(h1) = u1;
#pragma unroll
            for (int i = 0; i < 8; i++)
                ea2[(a8 * 8 + i) * 64 + k2] = h22u(__halves2half2(h0[i], h1[i]));
        }
        __syncthreads();

        int kb = k0 + kq * 8;
        if (k0 + 16 * w < Lmax) {
            float facc[8] = {0.f, 0.f, 0.f, 0.f, 0.f, 0.f, 0.f, 0.f};
            for (int a0 = 0; a0 < A_; a0 += 8) {
                __half2 h0 = hz, h1 = hz, h2 = hz, h3 = hz;
#pragma unroll
                for (int aa = 0; aa < 8; aa++) {
                    int a = a0 + aa;
                    uint4 e = *reinterpret_cast<uint4*>(&ea2[a * 64 + kq * 4]);
                    __half2 qh = u2h2(qa2[q * QA2STR + a]);
                    __half2 v2 = u2h2(vs2[a]);
                    h0 = __hfma2(v2, tanh2(__hadd2(qh, u2h2(e.x))), h0);
                    h1 = __hfma2(v2, tanh2(__hadd2(qh, u2h2(e.y))), h1);
                    h2 = __hfma2(v2, tanh2(__hadd2(qh, u2h2(e.z))), h2);
                    h3 = __hfma2(v2, tanh2(__hadd2(qh, u2h2(e.w))), h3);
                }
                float2 t0 = __half22float2(h0), t1 = __half22float2(h1);
                float2 t2 = __half22float2(h2), t3 = __half22float2(h3);
                facc[0] += t0.x; facc[1] += t0.y; facc[2] += t1.x; facc[3] += t1.y;
                facc[4] += t2.x; facc[5] += t2.y; facc[6] += t3.x; facc[7] += t3.y;
            }

            float sl = 0.f;
            __half2 o[4];
#pragma unroll
            for (int j = 0; j < 4; j++) {
                float w0 = (kb + 2 * j     < Lq) ? __expf(facc[2 * j])     : 0.f;
                float w1 = (kb + 2 * j + 1 < Lq) ? __expf(facc[2 * j + 1]) : 0.f;
                sl += w0 + w1;
                o[j] = __floats2half2_rn(w0, w1);
            }
            *reinterpret_cast<uint4*>(&g_wexp_h[wrow + kb]) = *reinterpret_cast<uint4*>(o);
            atomicAdd(&sums[q], sl);
        } else {
            uint4 z = {0u, 0u, 0u, 0u};
            *reinterpret_cast<uint4*>(&g_wexp_h[wrow + kb]) = z;
        }
    }
    __syncthreads();
    if (tid < SQ) g_rowsum[(q0 + tid) * B_ + b] = sums[tid];
}

// ---------------- normalize + transpose (b,q,k) -> weights (q,k,b) -------------
// One block per (q, 128-key tile). Sector-aligned 32B loads, float4 stores.
__global__ void __launch_bounds__(256) norm_transpose_kernel(float* __restrict__ wout)
{
    __shared__ float tile[32][129];
    __shared__ float inv_s[32];
    int tid = threadIdx.x;
    int q = blockIdx.y;
    int k0 = blockIdx.x * 128;
    int Lq = max(1, q - 1);

    if (tid < 32) inv_s[tid] = 1.f / g_rowsum[q * B_ + tid];

    bool any = (k0 < Lq);   // whole 128-tile written by score iff k0 < Lq
    if (any) {
        int bb = tid & 31;
        int kc = (tid >> 5) * 16;        // 16 halves = one 32B sector per thread
        const __half* p = g_wexp_h + ((size_t)bb * S_ + q) * S_ + k0 + kc;
#pragma unroll
        for (int u = 0; u < 2; u++) {
            uint4 raw = *reinterpret_cast<const uint4*>(p + u * 8);
            __half h[8]; *reinterpret_cast<uint4*>(h) = raw;
#pragma unroll
            for (int i = 0; i < 8; i++)
                tile[bb][kc + u * 8 + i] = __half2float(h[i]);
        }
    }
    __syncthreads();

    int b0 = (tid & 7) * 4;
    int kk = tid >> 3;                   // 0..31
#pragma unroll
    for (int p = 0; p < 4; p++) {
        int k = kk + p * 32;
        float4 vv = {0.f, 0.f, 0.f, 0.f};
        if (any && (k0 + k < Lq)) {
            vv.x = tile[b0 + 0][k] * inv_s[b0 + 0];
            vv.y = tile[b0 + 1][k] * inv_s[b0 + 1];
            vv.z = tile[b0 + 2][k] * inv_s[b0 + 2];
            vv.w = tile[b0 + 3][k] * inv_s[b0 + 3];
        }
        *reinterpret_cast<float4*>(&wout[((size_t)q * S_ + k0 + k) * B_ + b0]) = vv;
    }
}

// ---------------- launch --------------------------------------------------------
extern "C" void kernel_launch(void* const* d_in, const int* in_sizes, int n_in,
                              void* d_out, int out_size)
{
    const float* outs  = (const float*)d_in[0];
    const float* emb   = (const float*)d_in[1];
    const float* W_enc = (const float*)d_in[2];
    const float* b_enc = (const float*)d_in[3];
    const float* W_dec = (const float*)d_in[4];
    const float* b_dec = (const float*)d_in[5];
    const float* v     = (const float*)d_in[6];
    const float* W_h2h = (const float*)d_in[7];
    const float* b_h2h = (const float*)d_in[8];
    const float* W_e2h = (const float*)d_in[9];
    const float* b_e2h = (const float*)d_in[10];
    float* out = (float*)d_out;

    __half *p_outs_h, *p_emb_h, *p_wexp, *p_ctx, *p_Wh2h, *p_We2h;
    cudaGetSymbolAddress((void**)&p_outs_h, g_outs_h);
    cudaGetSymbolAddress((void**)&p_emb_h, g_emb_h);
    cudaGetSymbolAddress((void**)&p_Wh2h, g_Wh2h_h);
    cudaGetSymbolAddress((void**)&p_We2h, g_We2h_h);
    cudaGetSymbolAddress((void**)&p_wexp, g_wexp_h);
    cudaGetSymbolAddress((void**)&p_ctx, g_context_h);

    const int SMEM0 = STG * (ASZ + B0SZ) * 2;   // 61440 B
    const int SMEM1 = STG * (ASZ + B1SZ) * 2;   // 56832 B
    cudaFuncSetAttribute(hgemm_proj2, cudaFuncAttributeMaxDynamicSharedMemorySize, SMEM0);
    cudaFuncSetAttribute(hgemm<1>, cudaFuncAttributeMaxDynamicSharedMemorySize, SMEM1);
    cudaFuncSetAttribute(hgemm<2>, cudaFuncAttributeMaxDynamicSharedMemorySize, SMEM0);
    cudaFuncSetAttribute(score_kernel, cudaFuncAttributeMaxDynamicSharedMemorySize, SCORE_SMEM);

    const size_t OUT1 = (size_t)S_ * B_ * H_;
    const size_t WSZ  = (size_t)S_ * S_ * B_;
    bool hasW = ((size_t)out_size >= OUT1 + WSZ);

    // 0. all fp32->fp16 conversions in one launch
    const int FGROUPS = 2 * BIGN8 + WN0 + WN1 + WN2 + WN3;
    f2h_all_kernel<<<FGROUPS / 256, 256>>>(outs, emb, W_enc, W_dec, W_h2h, W_e2h);

    // 1. both projections in one launch
    hgemm_proj2<<<dim3((S_ * B_) / BM, A_ / BN, 2), 256, SMEM0>>>(b_enc, b_dec);

    // 2. scores + exp + rowsums (pure MUFU, heavy tiles first)
    score_kernel<<<dim3(S_ / SQ, B_), 256, SCORE_SMEM>>>(v);

    // 3. normalized weights output (q,k,b) — vectorized
    if (hasW)
        norm_transpose_kernel<<<dim3(S_ / 128, S_), 256>>>(out + OUT1);

    // 4. context (triangular K, heavy tiles first, fused 1/rowsum, half out)
    hgemm<1><<<dim3(S_ / BM, E_ / BN, B_), 256, SMEM1>>>(
        p_wexp, p_emb_h, nullptr, nullptr, nullptr, nullptr, p_ctx, E_, S_, 0);

    // 5. output = outs@W_h2h^T + ctx@W_e2h^T + biases (fused dual-K)
    hgemm<2><<<dim3((S_ * B_) / BM, H_ / BN), 256, SMEM0>>>(
        p_outs_h, p_Wh2h, p_ctx, p_We2h, b_h2h, b_e2h, out, H_, 1024, 0);
}